// round 2
// baseline (speedup 1.0000x reference)
#include <cuda_runtime.h>
#include <cuda_bf16.h>
#include <cstdint>

// Problem shape (fixed): B=4, S=1024, E=1024, H=16, D=64
#define BB 4
#define SS 1024
#define EE 1024
#define HH 16
#define DD 64

// ---------------------------------------------------------------------------
// Scratch (static __device__ globals — allocation-free per harness rules)
// ---------------------------------------------------------------------------
__device__ float g_Q[BB * SS * EE];
__device__ float g_K[BB * SS * EE];
__device__ float g_V[BB * SS * EE];
__device__ float g_A[BB * SS * EE];

// ---------------------------------------------------------------------------
// SGEMM:  Y[M,N] = X[M,K] @ W[N,K]^T + bias[N]
// Both operands K-major (row-major with K contiguous) -> NT layout.
// 128x128 block tile, BK=8, 8x8 per thread, 256 threads.
// ---------------------------------------------------------------------------
#define GBM 128
#define GBN 128
#define GBK 8
#define GTM 8
#define GTN 8

__global__ __launch_bounds__(256) void sgemm_nt_bias(
    const float* __restrict__ X, const float* __restrict__ W,
    const float* __restrict__ bias, float* __restrict__ Y,
    int M, int N, int K)
{
    __shared__ float As[GBK][GBM];
    __shared__ float Bs[GBK][GBN];

    const int tid = threadIdx.x;
    const int row0 = blockIdx.y * GBM;
    const int col0 = blockIdx.x * GBN;

    const int ld_row = tid >> 1;          // 0..127
    const int ld_col = (tid & 1) * 4;     // 0 or 4

    const int tx = tid & 15;              // 0..15
    const int ty = tid >> 4;              // 0..15

    float acc[GTM][GTN];
#pragma unroll
    for (int i = 0; i < GTM; i++)
#pragma unroll
        for (int j = 0; j < GTN; j++) acc[i][j] = 0.f;

    const float* Xp = X + (size_t)(row0 + ld_row) * K + ld_col;
    const float* Wp = W + (size_t)(col0 + ld_row) * K + ld_col;

    for (int k0 = 0; k0 < K; k0 += GBK) {
        float4 a = *(const float4*)(Xp + k0);
        float4 b = *(const float4*)(Wp + k0);
        As[ld_col + 0][ld_row] = a.x;
        As[ld_col + 1][ld_row] = a.y;
        As[ld_col + 2][ld_row] = a.z;
        As[ld_col + 3][ld_row] = a.w;
        Bs[ld_col + 0][ld_row] = b.x;
        Bs[ld_col + 1][ld_row] = b.y;
        Bs[ld_col + 2][ld_row] = b.z;
        Bs[ld_col + 3][ld_row] = b.w;
        __syncthreads();

#pragma unroll
        for (int k = 0; k < GBK; k++) {
            float ra[GTM], rb[GTN];
            *(float4*)&ra[0] = *(const float4*)&As[k][ty * GTM + 0];
            *(float4*)&ra[4] = *(const float4*)&As[k][ty * GTM + 4];
            *(float4*)&rb[0] = *(const float4*)&Bs[k][tx * GTN + 0];
            *(float4*)&rb[4] = *(const float4*)&Bs[k][tx * GTN + 4];
#pragma unroll
            for (int i = 0; i < GTM; i++)
#pragma unroll
                for (int j = 0; j < GTN; j++)
                    acc[i][j] += ra[i] * rb[j];
        }
        __syncthreads();
    }

#pragma unroll
    for (int i = 0; i < GTM; i++) {
        const int r = row0 + ty * GTM + i;
#pragma unroll
        for (int j = 0; j < GTN; j += 4) {
            const int c = col0 + tx * GTN + j;
            float4 o;
            o.x = acc[i][j + 0] + bias[c + 0];
            o.y = acc[i][j + 1] + bias[c + 1];
            o.z = acc[i][j + 2] + bias[c + 2];
            o.w = acc[i][j + 3] + bias[c + 3];
            *(float4*)&Y[(size_t)r * N + c] = o;
        }
    }
}

// ---------------------------------------------------------------------------
// Flash-attention (fp32, online softmax).
// grid = (S/128, H, B), block = 128 threads. Each thread owns one query row:
// Q row (64f) and O accumulator (64f) in registers; K/V tiles (64x64) in SMEM
// read via broadcast LDS.128. Mask folded as -1e30 before softmax.
// ---------------------------------------------------------------------------
#define FQT 128   // queries per block
#define FKT 64    // keys per tile

__global__ __launch_bounds__(128) void flash_attn_kernel(
    const float* __restrict__ Q, const float* __restrict__ K,
    const float* __restrict__ V, const int* __restrict__ mask,
    float* __restrict__ O)
{
    __shared__ float Ks[FKT][DD];
    __shared__ float Vs[FKT][DD];
    __shared__ int   ms[FKT];

    const int b  = blockIdx.z;
    const int h  = blockIdx.y;
    const int q0 = blockIdx.x * FQT;
    const int tid = threadIdx.x;

    const float scale = 0.03125f;  // 1/sqrt(E) = 1/32

    // Load this thread's query row into registers
    const float* qrow = Q + ((size_t)b * SS + q0 + tid) * EE + h * DD;
    float4 q[16];
#pragma unroll
    for (int i = 0; i < 16; i++) q[i] = *(const float4*)&qrow[i * 4];

    float4 o[16];
#pragma unroll
    for (int i = 0; i < 16; i++) o[i] = make_float4(0.f, 0.f, 0.f, 0.f);

    float m = -1e30f;
    float l = 0.f;

    for (int s0 = 0; s0 < SS; s0 += FKT) {
        // Cooperative K/V tile load (coalesced float4)
#pragma unroll
        for (int it = 0; it < (FKT * (DD / 4)) / 128; it++) {
            int idx = tid + it * 128;           // float4 index within tile
            int r = idx >> 4;                   // row (0..63)
            int c = (idx & 15) * 4;             // col
            size_t g = ((size_t)b * SS + s0 + r) * EE + h * DD + c;
            *(float4*)&Ks[r][c] = *(const float4*)&K[g];
            *(float4*)&Vs[r][c] = *(const float4*)&V[g];
        }
        if (tid < FKT) ms[tid] = mask[b * SS + s0 + tid];
        __syncthreads();

        for (int j = 0; j < FKT; j++) {
            // score = q . K[j]
            float4 s4 = make_float4(0.f, 0.f, 0.f, 0.f);
#pragma unroll
            for (int i = 0; i < 16; i++) {
                float4 kv = *(const float4*)&Ks[j][i * 4];
                s4.x += q[i].x * kv.x;
                s4.y += q[i].y * kv.y;
                s4.z += q[i].z * kv.z;
                s4.w += q[i].w * kv.w;
            }
            float s = (s4.x + s4.y) + (s4.z + s4.w);
            s = ms[j] ? s * scale : -1e30f;

            // online softmax: conditional rescale when max changes
            if (s > m) {
                float corr = __expf(m - s);
                m = s;
                l *= corr;
#pragma unroll
                for (int i = 0; i < 16; i++) {
                    o[i].x *= corr; o[i].y *= corr;
                    o[i].z *= corr; o[i].w *= corr;
                }
            }
            float p = __expf(s - m);
            l += p;
#pragma unroll
            for (int i = 0; i < 16; i++) {
                float4 vv = *(const float4*)&Vs[j][i * 4];
                o[i].x += p * vv.x;
                o[i].y += p * vv.y;
                o[i].z += p * vv.z;
                o[i].w += p * vv.w;
            }
        }
        __syncthreads();
    }

    const float inv = 1.f / l;
    float* orow = O + ((size_t)b * SS + q0 + tid) * EE + h * DD;
#pragma unroll
    for (int i = 0; i < 16; i++) {
        float4 ov;
        ov.x = o[i].x * inv; ov.y = o[i].y * inv;
        ov.z = o[i].z * inv; ov.w = o[i].w * inv;
        *(float4*)&orow[i * 4] = ov;
    }
}

// ---------------------------------------------------------------------------
// Launch
// Inputs (metadata order): value, key_in, query, mask,
//                          Wq, bq, Wk, bk, Wv, bv, Wo, bo
// ---------------------------------------------------------------------------
extern "C" void kernel_launch(void* const* d_in, const int* in_sizes, int n_in,
                              void* d_out, int out_size)
{
    const float* value  = (const float*)d_in[0];
    const float* key_in = (const float*)d_in[1];
    const float* query  = (const float*)d_in[2];
    const int*   mask   = (const int*)  d_in[3];
    const float* Wq = (const float*)d_in[4];
    const float* bq = (const float*)d_in[5];
    const float* Wk = (const float*)d_in[6];
    const float* bk = (const float*)d_in[7];
    const float* Wv = (const float*)d_in[8];
    const float* bv = (const float*)d_in[9];
    const float* Wo = (const float*)d_in[10];
    const float* bo = (const float*)d_in[11];
    float* out = (float*)d_out;

    float *dQ, *dK, *dV, *dA;
    cudaGetSymbolAddress((void**)&dQ, g_Q);
    cudaGetSymbolAddress((void**)&dK, g_K);
    cudaGetSymbolAddress((void**)&dV, g_V);
    cudaGetSymbolAddress((void**)&dA, g_A);

    const int M = BB * SS;   // 4096
    const int N = EE;        // 1024
    const int Kd = EE;       // 1024

    dim3 ggrid(N / GBN, M / GBM);   // (8, 32)
    dim3 gblk(256);

    sgemm_nt_bias<<<ggrid, gblk>>>(query,  Wq, bq, dQ, M, N, Kd);
    sgemm_nt_bias<<<ggrid, gblk>>>(key_in, Wk, bk, dK, M, N, Kd);
    sgemm_nt_bias<<<ggrid, gblk>>>(value,  Wv, bv, dV, M, N, Kd);

    dim3 fgrid(SS / FQT, HH, BB);   // (8, 16, 4)
    flash_attn_kernel<<<fgrid, 128>>>(dQ, dK, dV, mask, dA);

    sgemm_nt_bias<<<ggrid, gblk>>>(dA, Wo, bo, out, M, N, Kd);
}

// round 5
// speedup vs baseline: 1.6234x; 1.6234x over previous
#include <cuda_runtime.h>
#include <cuda_bf16.h>
#include <cstdint>

// Problem shape (fixed): B=4, S=1024, E=1024, H=16, D=64
#define BB 4
#define SS 1024
#define EE 1024
#define HH 16
#define DD 64

// ---------------------------------------------------------------------------
// Scratch (static __device__ globals — allocation-free per harness rules)
// ---------------------------------------------------------------------------
__device__ float g_Q[BB * SS * EE];
__device__ float g_K[BB * SS * EE];
__device__ float g_V[BB * SS * EE];
__device__ float g_A[BB * SS * EE];

// ---------------------------------------------------------------------------
// Helpers
// ---------------------------------------------------------------------------
__device__ __forceinline__ uint32_t f2tf32(float f) {
    uint32_t r;
    asm("cvt.rna.tf32.f32 %0, %1;" : "=r"(r) : "f"(f));
    return r;
}

// mma.sync m16n8k8 tf32: D(f32) += A(tf32) * B(tf32)
__device__ __forceinline__ void mma_tf32(float* c, const uint32_t* a, const uint32_t* b) {
    asm volatile(
        "mma.sync.aligned.m16n8k8.row.col.f32.tf32.tf32.f32 "
        "{%0,%1,%2,%3}, {%4,%5,%6,%7}, {%8,%9}, {%0,%1,%2,%3};"
        : "+f"(c[0]), "+f"(c[1]), "+f"(c[2]), "+f"(c[3])
        : "r"(a[0]), "r"(a[1]), "r"(a[2]), "r"(a[3]),
          "r"(b[0]), "r"(b[1]));
}

// ---------------------------------------------------------------------------
// Tensor-core tf32 GEMM:  Y[M,N] = X[M,K] @ W[N,K]^T + bias[N]
// CTA tile 128x128, BK=32, 256 threads = 8 warps (2m x 4n), 64x32 per warp.
// SMEM stride 36 floats -> conflict-free fragment LDS.
// ---------------------------------------------------------------------------
#define BM 128
#define BN 128
#define BK 32
#define LDT 36   // padded stride (floats)

__global__ __launch_bounds__(256, 2) void gemm_mma_tf32(
    const float* __restrict__ X, const float* __restrict__ W,
    const float* __restrict__ bias, float* __restrict__ Y,
    int M, int N, int K)
{
    __shared__ uint32_t As[BM * LDT];
    __shared__ uint32_t Bs[BN * LDT];

    const int tid = threadIdx.x;
    const int wid = tid >> 5;
    const int lane = tid & 31;
    const int lq = lane >> 2;   // 0..7
    const int lr = lane & 3;    // 0..3

    const int warp_m = wid >> 2;         // 0..1  (64 rows each)
    const int warp_n = wid & 3;          // 0..3  (32 cols each)
    const int wm = warp_m * 64;
    const int wn = warp_n * 32;

    const int row0 = blockIdx.y * BM;
    const int col0 = blockIdx.x * BN;

    // C accumulators: 4 mtiles x 4 ntiles x 4 frags
    float c[4][4][4];
#pragma unroll
    for (int m = 0; m < 4; m++)
#pragma unroll
        for (int n = 0; n < 4; n++)
#pragma unroll
            for (int f = 0; f < 4; f++) c[m][n][f] = 0.f;

    // Global load mapping: 256 threads, tile 128x32 floats
    const int lrow = tid >> 3;           // 0..31
    const int lc4  = (tid & 7) * 4;      // 0,4,...,28

    for (int k0 = 0; k0 < K; k0 += BK) {
#pragma unroll
        for (int i = 0; i < 4; i++) {
            const int r = lrow + i * 32;
            float4 a = *(const float4*)&X[(size_t)(row0 + r) * K + k0 + lc4];
            float4 w = *(const float4*)&W[(size_t)(col0 + r) * K + k0 + lc4];
            uint4 ta, tw;
            ta.x = f2tf32(a.x); ta.y = f2tf32(a.y); ta.z = f2tf32(a.z); ta.w = f2tf32(a.w);
            tw.x = f2tf32(w.x); tw.y = f2tf32(w.y); tw.z = f2tf32(w.z); tw.w = f2tf32(w.w);
            *(uint4*)&As[r * LDT + lc4] = ta;
            *(uint4*)&Bs[r * LDT + lc4] = tw;
        }
        __syncthreads();

#pragma unroll
        for (int kk = 0; kk < 4; kk++) {
            const int k8 = kk * 8;
            uint32_t afr[4][4], bfr[4][2];
#pragma unroll
            for (int m = 0; m < 4; m++) {
                const int base = (wm + m * 16 + lq) * LDT + k8 + lr;
                afr[m][0] = As[base];
                afr[m][1] = As[base + 8 * LDT];
                afr[m][2] = As[base + 4];
                afr[m][3] = As[base + 8 * LDT + 4];
            }
#pragma unroll
            for (int n = 0; n < 4; n++) {
                const int base = (wn + n * 8 + lq) * LDT + k8 + lr;
                bfr[n][0] = Bs[base];
                bfr[n][1] = Bs[base + 4];
            }
#pragma unroll
            for (int m = 0; m < 4; m++)
#pragma unroll
                for (int n = 0; n < 4; n++)
                    mma_tf32(c[m][n], afr[m], bfr[n]);
        }
        __syncthreads();
    }

    // Epilogue: fused bias, float2 stores
#pragma unroll
    for (int m = 0; m < 4; m++) {
        const int r_lo = row0 + wm + m * 16 + lq;
        const int r_hi = r_lo + 8;
#pragma unroll
        for (int n = 0; n < 4; n++) {
            const int col = col0 + wn + n * 8 + lr * 2;
            const float b0 = bias[col];
            const float b1 = bias[col + 1];
            float2 lo = make_float2(c[m][n][0] + b0, c[m][n][1] + b1);
            float2 hi = make_float2(c[m][n][2] + b0, c[m][n][3] + b1);
            *(float2*)&Y[(size_t)r_lo * N + col] = lo;
            *(float2*)&Y[(size_t)r_hi * N + col] = hi;
        }
    }
}

// ---------------------------------------------------------------------------
// Flash-attention (fp32, online softmax) — unchanged (proven, 783us).
// ---------------------------------------------------------------------------
#define FQT 128   // queries per block
#define FKT 64    // keys per tile

__global__ __launch_bounds__(128) void flash_attn_kernel(
    const float* __restrict__ Q, const float* __restrict__ K,
    const float* __restrict__ V, const int* __restrict__ mask,
    float* __restrict__ O)
{
    __shared__ float Ks[FKT][DD];
    __shared__ float Vs[FKT][DD];
    __shared__ int   ms[FKT];

    const int b  = blockIdx.z;
    const int h  = blockIdx.y;
    const int q0 = blockIdx.x * FQT;
    const int tid = threadIdx.x;

    const float scale = 0.03125f;  // 1/sqrt(E) = 1/32

    const float* qrow = Q + ((size_t)b * SS + q0 + tid) * EE + h * DD;
    float4 q[16];
#pragma unroll
    for (int i = 0; i < 16; i++) q[i] = *(const float4*)&qrow[i * 4];

    float4 o[16];
#pragma unroll
    for (int i = 0; i < 16; i++) o[i] = make_float4(0.f, 0.f, 0.f, 0.f);

    float m = -1e30f;
    float l = 0.f;

    for (int s0 = 0; s0 < SS; s0 += FKT) {
#pragma unroll
        for (int it = 0; it < (FKT * (DD / 4)) / 128; it++) {
            int idx = tid + it * 128;
            int r = idx >> 4;
            int cc = (idx & 15) * 4;
            size_t g = ((size_t)b * SS + s0 + r) * EE + h * DD + cc;
            *(float4*)&Ks[r][cc] = *(const float4*)&K[g];
            *(float4*)&Vs[r][cc] = *(const float4*)&V[g];
        }
        if (tid < FKT) ms[tid] = mask[b * SS + s0 + tid];
        __syncthreads();

        for (int j = 0; j < FKT; j++) {
            float4 s4 = make_float4(0.f, 0.f, 0.f, 0.f);
#pragma unroll
            for (int i = 0; i < 16; i++) {
                float4 kv = *(const float4*)&Ks[j][i * 4];
                s4.x += q[i].x * kv.x;
                s4.y += q[i].y * kv.y;
                s4.z += q[i].z * kv.z;
                s4.w += q[i].w * kv.w;
            }
            float s = (s4.x + s4.y) + (s4.z + s4.w);
            s = ms[j] ? s * scale : -1e30f;

            if (s > m) {
                float corr = __expf(m - s);
                m = s;
                l *= corr;
#pragma unroll
                for (int i = 0; i < 16; i++) {
                    o[i].x *= corr; o[i].y *= corr;
                    o[i].z *= corr; o[i].w *= corr;
                }
            }
            float p = __expf(s - m);
            l += p;
#pragma unroll
            for (int i = 0; i < 16; i++) {
                float4 vv = *(const float4*)&Vs[j][i * 4];
                o[i].x += p * vv.x;
                o[i].y += p * vv.y;
                o[i].z += p * vv.z;
                o[i].w += p * vv.w;
            }
        }
        __syncthreads();
    }

    const float inv = 1.f / l;
    float* orow = O + ((size_t)b * SS + q0 + tid) * EE + h * DD;
#pragma unroll
    for (int i = 0; i < 16; i++) {
        float4 ov;
        ov.x = o[i].x * inv; ov.y = o[i].y * inv;
        ov.z = o[i].z * inv; ov.w = o[i].w * inv;
        *(float4*)&orow[i * 4] = ov;
    }
}

// ---------------------------------------------------------------------------
// Launch
// Inputs (metadata order): value, key_in, query, mask,
//                          Wq, bq, Wk, bk, Wv, bv, Wo, bo
// ---------------------------------------------------------------------------
extern "C" void kernel_launch(void* const* d_in, const int* in_sizes, int n_in,
                              void* d_out, int out_size)
{
    const float* value  = (const float*)d_in[0];
    const float* key_in = (const float*)d_in[1];
    const float* query  = (const float*)d_in[2];
    const int*   mask   = (const int*)  d_in[3];
    const float* Wq = (const float*)d_in[4];
    const float* bq = (const float*)d_in[5];
    const float* Wk = (const float*)d_in[6];
    const float* bk = (const float*)d_in[7];
    const float* Wv = (const float*)d_in[8];
    const float* bv = (const float*)d_in[9];
    const float* Wo = (const float*)d_in[10];
    const float* bo = (const float*)d_in[11];
    float* out = (float*)d_out;

    float *dQ, *dK, *dV, *dA;
    cudaGetSymbolAddress((void**)&dQ, g_Q);
    cudaGetSymbolAddress((void**)&dK, g_K);
    cudaGetSymbolAddress((void**)&dV, g_V);
    cudaGetSymbolAddress((void**)&dA, g_A);

    const int M = BB * SS;   // 4096
    const int N = EE;        // 1024
    const int Kd = EE;       // 1024

    dim3 ggrid(N / BN, M / BM);   // (8, 32)

    gemm_mma_tf32<<<ggrid, 256>>>(query,  Wq, bq, dQ, M, N, Kd);
    gemm_mma_tf32<<<ggrid, 256>>>(key_in, Wk, bk, dK, M, N, Kd);
    gemm_mma_tf32<<<ggrid, 256>>>(value,  Wv, bv, dV, M, N, Kd);

    dim3 fgrid(SS / FQT, HH, BB);   // (8, 16, 4)
    flash_attn_kernel<<<fgrid, 128>>>(dQ, dK, dV, mask, dA);

    gemm_mma_tf32<<<ggrid, 256>>>(dA, Wo, bo, out, M, N, Kd);
}

// round 7
// speedup vs baseline: 3.5697x; 2.1989x over previous
#include <cuda_runtime.h>
#include <cuda_bf16.h>
#include <cstdint>

// Problem shape (fixed): B=4, S=1024, E=1024, H=16, D=64
#define BB 4
#define SS 1024
#define EE 1024
#define HH 16
#define DD 64

// ---------------------------------------------------------------------------
// Scratch (static __device__ globals — allocation-free per harness rules)
// ---------------------------------------------------------------------------
__device__ float g_Q[BB * SS * EE];
__device__ float g_K[BB * SS * EE];
__device__ float g_V[BB * SS * EE];
__device__ float g_A[BB * SS * EE];

// ---------------------------------------------------------------------------
// Helpers
// ---------------------------------------------------------------------------
__device__ __forceinline__ uint32_t f2tf32(float f) {
    uint32_t r;
    asm("cvt.rna.tf32.f32 %0, %1;" : "=r"(r) : "f"(f));
    return r;
}

// mma.sync m16n8k8 tf32: D(f32) += A(tf32) * B(tf32)
__device__ __forceinline__ void mma_tf32(float* c, const uint32_t* a, const uint32_t* b) {
    asm volatile(
        "mma.sync.aligned.m16n8k8.row.col.f32.tf32.tf32.f32 "
        "{%0,%1,%2,%3}, {%4,%5,%6,%7}, {%8,%9}, {%0,%1,%2,%3};"
        : "+f"(c[0]), "+f"(c[1]), "+f"(c[2]), "+f"(c[3])
        : "r"(a[0]), "r"(a[1]), "r"(a[2]), "r"(a[3]),
          "r"(b[0]), "r"(b[1]));
}

// FMA-pipe exp2 for x <= 0 (clamped at -126). ~4e-5 abs err.
__device__ __forceinline__ float fexp2(float x) {
    x = fmaxf(x, -126.0f);
    float z = x + 12582912.0f;            // round-to-nearest-int in mantissa
    int   i = __float_as_int(z);          // low bits hold the integer
    float f = x - (z - 12582912.0f);      // f in [-0.5, 0.5]
    float p = 9.6181e-3f;
    p = fmaf(p, f, 5.55041e-2f);
    p = fmaf(p, f, 2.402265e-1f);
    p = fmaf(p, f, 6.931472e-1f);
    p = fmaf(p, f, 1.0f);
    return __int_as_float(__float_as_int(p) + (i << 23));
}

// ---------------------------------------------------------------------------
// Tensor-core tf32 GEMM:  Y[M,N] = X[M,K] @ W[N,K]^T + bias[N]
// (unchanged from R4 — passing at ~70us each)
// ---------------------------------------------------------------------------
#define BM 128
#define BN 128
#define BK 32
#define LDT 36   // padded stride (floats)

__global__ __launch_bounds__(256, 2) void gemm_mma_tf32(
    const float* __restrict__ X, const float* __restrict__ W,
    const float* __restrict__ bias, float* __restrict__ Y,
    int M, int N, int K)
{
    __shared__ uint32_t As[BM * LDT];
    __shared__ uint32_t Bs[BN * LDT];

    const int tid = threadIdx.x;
    const int wid = tid >> 5;
    const int lane = tid & 31;
    const int lq = lane >> 2;
    const int lr = lane & 3;

    const int warp_m = wid >> 2;
    const int warp_n = wid & 3;
    const int wm = warp_m * 64;
    const int wn = warp_n * 32;

    const int row0 = blockIdx.y * BM;
    const int col0 = blockIdx.x * BN;

    float c[4][4][4];
#pragma unroll
    for (int m = 0; m < 4; m++)
#pragma unroll
        for (int n = 0; n < 4; n++)
#pragma unroll
            for (int f = 0; f < 4; f++) c[m][n][f] = 0.f;

    const int lrow = tid >> 3;
    const int lc4  = (tid & 7) * 4;

    for (int k0 = 0; k0 < K; k0 += BK) {
#pragma unroll
        for (int i = 0; i < 4; i++) {
            const int r = lrow + i * 32;
            float4 a = *(const float4*)&X[(size_t)(row0 + r) * K + k0 + lc4];
            float4 w = *(const float4*)&W[(size_t)(col0 + r) * K + k0 + lc4];
            uint4 ta, tw;
            ta.x = f2tf32(a.x); ta.y = f2tf32(a.y); ta.z = f2tf32(a.z); ta.w = f2tf32(a.w);
            tw.x = f2tf32(w.x); tw.y = f2tf32(w.y); tw.z = f2tf32(w.z); tw.w = f2tf32(w.w);
            *(uint4*)&As[r * LDT + lc4] = ta;
            *(uint4*)&Bs[r * LDT + lc4] = tw;
        }
        __syncthreads();

#pragma unroll
        for (int kk = 0; kk < 4; kk++) {
            const int k8 = kk * 8;
            uint32_t afr[4][4], bfr[4][2];
#pragma unroll
            for (int m = 0; m < 4; m++) {
                const int base = (wm + m * 16 + lq) * LDT + k8 + lr;
                afr[m][0] = As[base];
                afr[m][1] = As[base + 8 * LDT];
                afr[m][2] = As[base + 4];
                afr[m][3] = As[base + 8 * LDT + 4];
            }
#pragma unroll
            for (int n = 0; n < 4; n++) {
                const int base = (wn + n * 8 + lq) * LDT + k8 + lr;
                bfr[n][0] = Bs[base];
                bfr[n][1] = Bs[base + 4];
            }
#pragma unroll
            for (int m = 0; m < 4; m++)
#pragma unroll
                for (int n = 0; n < 4; n++)
                    mma_tf32(c[m][n], afr[m], bfr[n]);
        }
        __syncthreads();
    }

#pragma unroll
    for (int m = 0; m < 4; m++) {
        const int r_lo = row0 + wm + m * 16 + lq;
        const int r_hi = r_lo + 8;
#pragma unroll
        for (int n = 0; n < 4; n++) {
            const int col = col0 + wn + n * 8 + lr * 2;
            const float b0 = bias[col];
            const float b1 = bias[col + 1];
            float2 lo = make_float2(c[m][n][0] + b0, c[m][n][1] + b1);
            float2 hi = make_float2(c[m][n][2] + b0, c[m][n][3] + b1);
            *(float2*)&Y[(size_t)r_lo * N + col] = lo;
            *(float2*)&Y[(size_t)r_hi * N + col] = hi;
        }
    }
}

// ---------------------------------------------------------------------------
// Tensor-core flash attention (tf32 mma + base-2 FMA softmax).
// grid = (S/128, H, B), block = 256 (8 warps). Warp w owns q-rows w*16..w*16+15
// across ALL keys -> softmax stats stay inside a quad (shfl xor 1,2).
// Key tile = 64.
// Strides: Q/K/P = 68 (68%32=4 -> frag pattern 4*lq+lr conflict-free),
//          V = 72 (72%32=8 -> frag pattern 8*lr+lq conflict-free).
// ---------------------------------------------------------------------------
#define FA_THREADS 256
#define SKT 64
#define QSTR 68
#define KSTR 68
#define PSTR 68
#define VSTR 72

// smem offsets in uint32 units
#define OFF_Q 0
#define OFF_K (128 * QSTR)                    // 8704
#define OFF_V (OFF_K + 64 * KSTR)             // 13056
#define OFF_P (OFF_V + 64 * VSTR)             // 17664
#define OFF_M (OFF_P + 128 * PSTR)            // 26368
#define FA_SMEM_U32 (OFF_M + 64)              // 26432
#define FA_SMEM_BYTES (FA_SMEM_U32 * 4)       // 105728

__global__ __launch_bounds__(FA_THREADS) void flash_mma_kernel(
    const float* __restrict__ Q, const float* __restrict__ K,
    const float* __restrict__ V, const int* __restrict__ mask,
    float* __restrict__ O)
{
    extern __shared__ uint32_t sm[];
    uint32_t* Qs = sm + OFF_Q;     // [128][QSTR]
    uint32_t* Ks = sm + OFF_K;     // [64][KSTR]
    uint32_t* Vs = sm + OFF_V;     // [64][VSTR]
    uint32_t* Ps = sm + OFF_P;     // [128][PSTR]
    float*   msf = (float*)(sm + OFF_M);

    const int b  = blockIdx.z;
    const int h  = blockIdx.y;
    const int q0 = blockIdx.x * 128;
    const int tid = threadIdx.x;
    const int wid = tid >> 5;
    const int lane = tid & 31;
    const int lq = lane >> 2;
    const int lr = lane & 3;
    const int wm = wid * 16;

    const float C = 0.0450842200f;   // log2(e) / 32

    // --- load Q tile (tf32) ---
    const float* Qg = Q + ((size_t)b * SS + q0) * EE + h * DD;
#pragma unroll
    for (int it = 0; it < 8; it++) {
        int idx = tid + it * 256;         // 0..2047
        int r = idx >> 4, c4 = (idx & 15) * 4;
        float4 v = *(const float4*)&Qg[(size_t)r * EE + c4];
        Qs[r * QSTR + c4 + 0] = f2tf32(v.x);
        Qs[r * QSTR + c4 + 1] = f2tf32(v.y);
        Qs[r * QSTR + c4 + 2] = f2tf32(v.z);
        Qs[r * QSTR + c4 + 3] = f2tf32(v.w);
    }

    float o[8][4];
#pragma unroll
    for (int n = 0; n < 8; n++)
#pragma unroll
        for (int f = 0; f < 4; f++) o[n][f] = 0.f;

    float m0 = -1e30f, m1 = -1e30f, l0 = 0.f, l1 = 0.f;

    const float* Kg = K + (size_t)b * SS * EE + h * DD;
    const float* Vg = V + (size_t)b * SS * EE + h * DD;

    for (int s0 = 0; s0 < SS; s0 += SKT) {
        __syncthreads();   // smem reuse guard (also publishes Qs on iter 0)
#pragma unroll
        for (int it = 0; it < 4; it++) {
            int idx = tid + it * 256;     // 0..1023
            int r = idx >> 4, c4 = (idx & 15) * 4;
            float4 kv = *(const float4*)&Kg[(size_t)(s0 + r) * EE + c4];
            float4 vv = *(const float4*)&Vg[(size_t)(s0 + r) * EE + c4];
            Ks[r * KSTR + c4 + 0] = f2tf32(kv.x);
            Ks[r * KSTR + c4 + 1] = f2tf32(kv.y);
            Ks[r * KSTR + c4 + 2] = f2tf32(kv.z);
            Ks[r * KSTR + c4 + 3] = f2tf32(kv.w);
            Vs[r * VSTR + c4 + 0] = f2tf32(vv.x);
            Vs[r * VSTR + c4 + 1] = f2tf32(vv.y);
            Vs[r * VSTR + c4 + 2] = f2tf32(vv.z);
            Vs[r * VSTR + c4 + 3] = f2tf32(vv.w);
        }
        if (tid < SKT) msf[tid] = mask[b * SS + s0 + tid] ? 0.0f : -1e30f;
        __syncthreads();

        // --- scores S = Q . K^T  (16 rows x 64 keys per warp) ---
        float s[8][4];
#pragma unroll
        for (int n = 0; n < 8; n++)
#pragma unroll
            for (int f = 0; f < 4; f++) s[n][f] = 0.f;

#pragma unroll
        for (int kk = 0; kk < 8; kk++) {
            uint32_t a[4];
            const int ab = (wm + lq) * QSTR + kk * 8 + lr;
            a[0] = Qs[ab];
            a[1] = Qs[ab + 8 * QSTR];
            a[2] = Qs[ab + 4];
            a[3] = Qs[ab + 8 * QSTR + 4];
#pragma unroll
            for (int n = 0; n < 8; n++) {
                uint32_t bf[2];
                const int bb2 = (n * 8 + lq) * KSTR + kk * 8 + lr;
                bf[0] = Ks[bb2];
                bf[1] = Ks[bb2 + 4];
                mma_tf32(s[n], a, bf);
            }
        }

        // --- mask + scale (base-2 domain), tile row max ---
        float tmax0 = -1e30f, tmax1 = -1e30f;
#pragma unroll
        for (int n = 0; n < 8; n++) {
            const float mf0 = msf[n * 8 + 2 * lr];
            const float mf1 = msf[n * 8 + 2 * lr + 1];
            s[n][0] = fmaf(s[n][0], C, mf0);
            s[n][1] = fmaf(s[n][1], C, mf1);
            s[n][2] = fmaf(s[n][2], C, mf0);
            s[n][3] = fmaf(s[n][3], C, mf1);
            tmax0 = fmaxf(tmax0, fmaxf(s[n][0], s[n][1]));
            tmax1 = fmaxf(tmax1, fmaxf(s[n][2], s[n][3]));
        }
        tmax0 = fmaxf(tmax0, __shfl_xor_sync(0xffffffffu, tmax0, 1));
        tmax0 = fmaxf(tmax0, __shfl_xor_sync(0xffffffffu, tmax0, 2));
        tmax1 = fmaxf(tmax1, __shfl_xor_sync(0xffffffffu, tmax1, 1));
        tmax1 = fmaxf(tmax1, __shfl_xor_sync(0xffffffffu, tmax1, 2));

        const float mn0 = fmaxf(m0, tmax0);
        const float mn1 = fmaxf(m1, tmax1);
        const float c0 = fexp2(m0 - mn0);
        const float c1 = fexp2(m1 - mn1);
        m0 = mn0; m1 = mn1;
        l0 *= c0;  l1 *= c1;

        // --- p = 2^(s-m): rescale O, accumulate l, stage P (tf32) ---
#pragma unroll
        for (int n = 0; n < 8; n++) {
            o[n][0] *= c0; o[n][1] *= c0; o[n][2] *= c1; o[n][3] *= c1;
            const float p0 = fexp2(s[n][0] - m0);
            const float p1 = fexp2(s[n][1] - m0);
            const float p2 = fexp2(s[n][2] - m1);
            const float p3 = fexp2(s[n][3] - m1);
            l0 += p0 + p1;
            l1 += p2 + p3;
            const int pb = (wm + lq) * PSTR + n * 8 + 2 * lr;
            Ps[pb]               = f2tf32(p0);
            Ps[pb + 1]           = f2tf32(p1);
            Ps[pb + 8 * PSTR]     = f2tf32(p2);
            Ps[pb + 8 * PSTR + 1] = f2tf32(p3);
        }
        __syncwarp();   // publish P stores to all lanes of this warp

        // --- O += P . V  (P rows are warp-private; V published at tile sync) ---
#pragma unroll
        for (int kk = 0; kk < 8; kk++) {
            uint32_t a[4];
            const int ab = (wm + lq) * PSTR + kk * 8 + lr;
            a[0] = Ps[ab];
            a[1] = Ps[ab + 8 * PSTR];
            a[2] = Ps[ab + 4];
            a[3] = Ps[ab + 8 * PSTR + 4];
#pragma unroll
            for (int n = 0; n < 8; n++) {
                uint32_t bf[2];
                bf[0] = Vs[(kk * 8 + lr) * VSTR + n * 8 + lq];
                bf[1] = Vs[(kk * 8 + lr + 4) * VSTR + n * 8 + lq];
                mma_tf32(o[n], a, bf);
            }
        }
    }

    // --- finalize: quad-sum l, divide, store ---
    l0 += __shfl_xor_sync(0xffffffffu, l0, 1);
    l0 += __shfl_xor_sync(0xffffffffu, l0, 2);
    l1 += __shfl_xor_sync(0xffffffffu, l1, 1);
    l1 += __shfl_xor_sync(0xffffffffu, l1, 2);
    const float inv0 = 1.0f / l0;
    const float inv1 = 1.0f / l1;

    float* Og = O + ((size_t)b * SS + q0 + wm + lq) * EE + h * DD;
#pragma unroll
    for (int n = 0; n < 8; n++) {
        *(float2*)&Og[n * 8 + 2 * lr] =
            make_float2(o[n][0] * inv0, o[n][1] * inv0);
        *(float2*)&Og[(size_t)8 * EE + n * 8 + 2 * lr] =
            make_float2(o[n][2] * inv1, o[n][3] * inv1);
    }
}

// ---------------------------------------------------------------------------
// Launch
// Inputs (metadata order): value, key_in, query, mask,
//                          Wq, bq, Wk, bk, Wv, bv, Wo, bo
// ---------------------------------------------------------------------------
extern "C" void kernel_launch(void* const* d_in, const int* in_sizes, int n_in,
                              void* d_out, int out_size)
{
    const float* value  = (const float*)d_in[0];
    const float* key_in = (const float*)d_in[1];
    const float* query  = (const float*)d_in[2];
    const int*   mask   = (const int*)  d_in[3];
    const float* Wq = (const float*)d_in[4];
    const float* bq = (const float*)d_in[5];
    const float* Wk = (const float*)d_in[6];
    const float* bk = (const float*)d_in[7];
    const float* Wv = (const float*)d_in[8];
    const float* bv = (const float*)d_in[9];
    const float* Wo = (const float*)d_in[10];
    const float* bo = (const float*)d_in[11];
    float* out = (float*)d_out;

    float *dQ, *dK, *dV, *dA;
    cudaGetSymbolAddress((void**)&dQ, g_Q);
    cudaGetSymbolAddress((void**)&dK, g_K);
    cudaGetSymbolAddress((void**)&dV, g_V);
    cudaGetSymbolAddress((void**)&dA, g_A);

    cudaFuncSetAttribute(flash_mma_kernel,
                         cudaFuncAttributeMaxDynamicSharedMemorySize, FA_SMEM_BYTES);

    const int M = BB * SS;   // 4096
    const int N = EE;        // 1024
    const int Kd = EE;       // 1024

    dim3 ggrid(N / BN, M / BM);   // (8, 32)

    gemm_mma_tf32<<<ggrid, 256>>>(query,  Wq, bq, dQ, M, N, Kd);
    gemm_mma_tf32<<<ggrid, 256>>>(key_in, Wk, bk, dK, M, N, Kd);
    gemm_mma_tf32<<<ggrid, 256>>>(value,  Wv, bv, dV, M, N, Kd);

    dim3 fgrid(SS / 128, HH, BB);   // (8, 16, 4)
    flash_mma_kernel<<<fgrid, FA_THREADS, FA_SMEM_BYTES>>>(dQ, dK, dV, mask, dA);

    gemm_mma_tf32<<<ggrid, 256>>>(dA, Wo, bo, out, M, N, Kd);
}

// round 8
// speedup vs baseline: 3.9897x; 1.1177x over previous
#include <cuda_runtime.h>
#include <cuda_bf16.h>
#include <cstdint>

// Problem shape (fixed): B=4, S=1024, E=1024, H=16, D=64
#define BB 4
#define SS 1024
#define EE 1024
#define HH 16
#define DD 64

// ---------------------------------------------------------------------------
// Scratch (static __device__ globals — allocation-free per harness rules)
// ---------------------------------------------------------------------------
__device__ float g_Q[BB * SS * EE];
__device__ float g_K[BB * SS * EE];
__device__ float g_V[BB * SS * EE];
__device__ float g_A[BB * SS * EE];

// ---------------------------------------------------------------------------
// Helpers
// ---------------------------------------------------------------------------
__device__ __forceinline__ uint32_t smem_u32(const void* p) {
    uint32_t a;
    asm("{ .reg .u64 t; cvta.to.shared.u64 t, %1; cvt.u32.u64 %0, t; }"
        : "=r"(a) : "l"(p));
    return a;
}

__device__ __forceinline__ uint32_t f2tf32(float f) {
    uint32_t r;
    asm("cvt.rna.tf32.f32 %0, %1;" : "=r"(r) : "f"(f));
    return r;
}

// mma.sync m16n8k8 tf32: D(f32) += A(tf32) * B(tf32)
__device__ __forceinline__ void mma_tf32(float* c, const uint32_t* a, const uint32_t* b) {
    asm volatile(
        "mma.sync.aligned.m16n8k8.row.col.f32.tf32.tf32.f32 "
        "{%0,%1,%2,%3}, {%4,%5,%6,%7}, {%8,%9}, {%0,%1,%2,%3};"
        : "+f"(c[0]), "+f"(c[1]), "+f"(c[2]), "+f"(c[3])
        : "r"(a[0]), "r"(a[1]), "r"(a[2]), "r"(a[3]),
          "r"(b[0]), "r"(b[1]));
}

// ldmatrix x4 (non-trans). Lane l of matrix i receives (row l>>2, f32col l&3).
__device__ __forceinline__ void ldsm4(uint32_t& r0, uint32_t& r1,
                                      uint32_t& r2, uint32_t& r3, uint32_t addr) {
    asm volatile(
        "ldmatrix.sync.aligned.m8n8.x4.shared.b16 {%0,%1,%2,%3}, [%4];"
        : "=r"(r0), "=r"(r1), "=r"(r2), "=r"(r3) : "r"(addr));
}

__device__ __forceinline__ void cp16(uint32_t dst, const void* src) {
    asm volatile("cp.async.cg.shared.global [%0], [%1], 16;"
                 :: "r"(dst), "l"(src));
}
__device__ __forceinline__ void cp_commit() {
    asm volatile("cp.async.commit_group;");
}
__device__ __forceinline__ void cp_wait0() {
    asm volatile("cp.async.wait_group 0;" ::: "memory");
}

// FMA-pipe exp2 for x <= 0 (clamped at -126). ~4e-5 abs err.
__device__ __forceinline__ float fexp2(float x) {
    x = fmaxf(x, -126.0f);
    float z = x + 12582912.0f;
    int   i = __float_as_int(z);
    float f = x - (z - 12582912.0f);
    float p = 9.6181e-3f;
    p = fmaf(p, f, 5.55041e-2f);
    p = fmaf(p, f, 2.402265e-1f);
    p = fmaf(p, f, 6.931472e-1f);
    p = fmaf(p, f, 1.0f);
    return __int_as_float(__float_as_int(p) + (i << 23));
}

// ---------------------------------------------------------------------------
// GEMM v2:  Y[M,N] = X[M,K] @ W[N,K]^T + bias[N]
// CTA 256x128, 8 warps (4m x 2n) of 64x64. BK=32. cp.async double buffer.
// Raw fp32 in smem (stride 36); cvt->tf32 at fragment load via ldmatrix.
// ---------------------------------------------------------------------------
#define BM2 256
#define BN2 128
#define BK2 32
#define LD2 36

#define G2_ABUF (BM2 * LD2)                    // 9216 u32
#define G2_BBUF (BN2 * LD2)                    // 4608 u32
#define G2_STAGE (G2_ABUF + G2_BBUF)           // 13824 u32
#define G2_SMEM_BYTES (2 * G2_STAGE * 4)       // 110592 B

__global__ __launch_bounds__(256) void gemm2_tf32(
    const float* __restrict__ X, const float* __restrict__ W,
    const float* __restrict__ bias, float* __restrict__ Y,
    int M, int N, int K)
{
    extern __shared__ uint32_t smg[];
    const uint32_t sb = smem_u32(smg);

    const int tid = threadIdx.x;
    const int wid = tid >> 5;
    const int lane = tid & 31;
    const int lq = lane >> 2;
    const int lr = lane & 3;

    const int wm = (wid >> 1) * 64;     // 0,64,128,192
    const int wn = (wid & 1) * 64;      // 0,64

    const int row0 = blockIdx.y * BM2;
    const int col0 = blockIdx.x * BN2;

    float c[4][8][4];
#pragma unroll
    for (int m = 0; m < 4; m++)
#pragma unroll
        for (int n = 0; n < 8; n++)
#pragma unroll
            for (int f = 0; f < 4; f++) c[m][n][f] = 0.f;

    // loader mapping
    const int lrow = tid >> 3;          // 0..31
    const int lc4  = (tid & 7) * 4;     // 0..28

    // ldmatrix lane address components
    const int aRow = wm + (lane & 15);
    const int aCol = (lane >> 4) * 4;
    const int bRow = wn + ((lane >> 4) << 3) + (lane & 7);
    const int bCol = ((lane >> 3) & 1) * 4;

    const int nstages = K / BK2;        // 32

    // prologue: stage 0
    {
        const int k0 = 0;
#pragma unroll
        for (int i = 0; i < 8; i++) {
            const int r = lrow + i * 32;
            cp16(sb + (uint32_t)(r * LD2 + lc4) * 4,
                 &X[(size_t)(row0 + r) * K + k0 + lc4]);
        }
#pragma unroll
        for (int i = 0; i < 4; i++) {
            const int r = lrow + i * 32;
            cp16(sb + (uint32_t)(G2_ABUF + r * LD2 + lc4) * 4,
                 &W[(size_t)(col0 + r) * K + k0 + lc4]);
        }
        cp_commit();
    }

#pragma unroll 1
    for (int s = 0; s < nstages; s++) {
        cp_wait0();
        __syncthreads();

        if (s + 1 < nstages) {
            const int b1 = (s + 1) & 1;
            const int k0 = (s + 1) * BK2;
            const uint32_t ab = sb + (uint32_t)(b1 * G2_STAGE) * 4;
#pragma unroll
            for (int i = 0; i < 8; i++) {
                const int r = lrow + i * 32;
                cp16(ab + (uint32_t)(r * LD2 + lc4) * 4,
                     &X[(size_t)(row0 + r) * K + k0 + lc4]);
            }
#pragma unroll
            for (int i = 0; i < 4; i++) {
                const int r = lrow + i * 32;
                cp16(ab + (uint32_t)(G2_ABUF + r * LD2 + lc4) * 4,
                     &W[(size_t)(col0 + r) * K + k0 + lc4]);
            }
            cp_commit();
        }

        const uint32_t abase = sb + (uint32_t)((s & 1) * G2_STAGE) * 4;
        const uint32_t bbase = abase + (uint32_t)G2_ABUF * 4;

#pragma unroll
        for (int kk = 0; kk < 4; kk++) {
            const int k8 = kk * 8;
            uint32_t a[4][4], bf[8][2];
#pragma unroll
            for (int m = 0; m < 4; m++) {
                uint32_t r0, r1, r2, r3;
                ldsm4(r0, r1, r2, r3,
                      abase + (uint32_t)((aRow + m * 16) * LD2 + k8 + aCol) * 4);
                a[m][0] = f2tf32(__uint_as_float(r0));
                a[m][1] = f2tf32(__uint_as_float(r1));
                a[m][2] = f2tf32(__uint_as_float(r2));
                a[m][3] = f2tf32(__uint_as_float(r3));
            }
#pragma unroll
            for (int p = 0; p < 4; p++) {
                uint32_t r0, r1, r2, r3;
                ldsm4(r0, r1, r2, r3,
                      bbase + (uint32_t)((bRow + p * 16) * LD2 + k8 + bCol) * 4);
                bf[2 * p][0]     = f2tf32(__uint_as_float(r0));
                bf[2 * p][1]     = f2tf32(__uint_as_float(r1));
                bf[2 * p + 1][0] = f2tf32(__uint_as_float(r2));
                bf[2 * p + 1][1] = f2tf32(__uint_as_float(r3));
            }
#pragma unroll
            for (int m = 0; m < 4; m++)
#pragma unroll
                for (int n = 0; n < 8; n++)
                    mma_tf32(c[m][n], a[m], bf[n]);
        }
    }

    // epilogue: fused bias
#pragma unroll
    for (int m = 0; m < 4; m++) {
        const int r_lo = row0 + wm + m * 16 + lq;
        const int r_hi = r_lo + 8;
#pragma unroll
        for (int n = 0; n < 8; n++) {
            const int col = col0 + wn + n * 8 + lr * 2;
            const float b0 = bias[col];
            const float b1 = bias[col + 1];
            *(float2*)&Y[(size_t)r_lo * N + col] =
                make_float2(c[m][n][0] + b0, c[m][n][1] + b1);
            *(float2*)&Y[(size_t)r_hi * N + col] =
                make_float2(c[m][n][2] + b0, c[m][n][3] + b1);
        }
    }
}

// ---------------------------------------------------------------------------
// Tensor-core flash attention (tf32 mma + base-2 FMA softmax).
// Q/K/P fragment loads via ldmatrix; V scalar (trans pattern). Layout as R6.
// ---------------------------------------------------------------------------
#define FA_THREADS 256
#define SKT 64
#define QSTR 68
#define KSTR 68
#define PSTR 68
#define VSTR 72

#define OFF_Q 0
#define OFF_K (128 * QSTR)                    // 8704
#define OFF_V (OFF_K + 64 * KSTR)             // 13056
#define OFF_P (OFF_V + 64 * VSTR)             // 17664
#define OFF_M (OFF_P + 128 * PSTR)            // 26368
#define FA_SMEM_U32 (OFF_M + 64)              // 26432
#define FA_SMEM_BYTES (FA_SMEM_U32 * 4)       // 105728

__global__ __launch_bounds__(FA_THREADS) void flash_mma_kernel(
    const float* __restrict__ Q, const float* __restrict__ K,
    const float* __restrict__ V, const int* __restrict__ mask,
    float* __restrict__ O)
{
    extern __shared__ uint32_t sm[];
    uint32_t* Qs = sm + OFF_Q;
    uint32_t* Ks = sm + OFF_K;
    uint32_t* Vs = sm + OFF_V;
    uint32_t* Ps = sm + OFF_P;
    float*   msf = (float*)(sm + OFF_M);
    const uint32_t sb = smem_u32(sm);

    const int b  = blockIdx.z;
    const int h  = blockIdx.y;
    const int q0 = blockIdx.x * 128;
    const int tid = threadIdx.x;
    const int wid = tid >> 5;
    const int lane = tid & 31;
    const int lq = lane >> 2;
    const int lr = lane & 3;
    const int wm = wid * 16;

    const float C = 0.0450842200f;   // log2(e) / 32

    // ldmatrix lane addresses (byte units)
    const uint32_t qa = sb + (uint32_t)(OFF_Q + (wm + (lane & 15)) * QSTR
                                        + ((lane >> 4) << 2)) * 4;
    const uint32_t ka = sb + (uint32_t)(OFF_K + (((lane >> 4) << 3) + (lane & 7)) * KSTR
                                        + (((lane >> 3) & 1) << 2)) * 4;
    const uint32_t pa = sb + (uint32_t)(OFF_P + (wm + (lane & 15)) * PSTR
                                        + ((lane >> 4) << 2)) * 4;

    // --- load Q tile (tf32) ---
    const float* Qg = Q + ((size_t)b * SS + q0) * EE + h * DD;
#pragma unroll
    for (int it = 0; it < 8; it++) {
        int idx = tid + it * 256;
        int r = idx >> 4, c4 = (idx & 15) * 4;
        float4 v = *(const float4*)&Qg[(size_t)r * EE + c4];
        Qs[r * QSTR + c4 + 0] = f2tf32(v.x);
        Qs[r * QSTR + c4 + 1] = f2tf32(v.y);
        Qs[r * QSTR + c4 + 2] = f2tf32(v.z);
        Qs[r * QSTR + c4 + 3] = f2tf32(v.w);
    }

    float o[8][4];
#pragma unroll
    for (int n = 0; n < 8; n++)
#pragma unroll
        for (int f = 0; f < 4; f++) o[n][f] = 0.f;

    float m0 = -1e30f, m1 = -1e30f, l0 = 0.f, l1 = 0.f;

    const float* Kg = K + (size_t)b * SS * EE + h * DD;
    const float* Vg = V + (size_t)b * SS * EE + h * DD;

    for (int s0 = 0; s0 < SS; s0 += SKT) {
        __syncthreads();
#pragma unroll
        for (int it = 0; it < 4; it++) {
            int idx = tid + it * 256;
            int r = idx >> 4, c4 = (idx & 15) * 4;
            float4 kv = *(const float4*)&Kg[(size_t)(s0 + r) * EE + c4];
            float4 vv = *(const float4*)&Vg[(size_t)(s0 + r) * EE + c4];
            Ks[r * KSTR + c4 + 0] = f2tf32(kv.x);
            Ks[r * KSTR + c4 + 1] = f2tf32(kv.y);
            Ks[r * KSTR + c4 + 2] = f2tf32(kv.z);
            Ks[r * KSTR + c4 + 3] = f2tf32(kv.w);
            Vs[r * VSTR + c4 + 0] = f2tf32(vv.x);
            Vs[r * VSTR + c4 + 1] = f2tf32(vv.y);
            Vs[r * VSTR + c4 + 2] = f2tf32(vv.z);
            Vs[r * VSTR + c4 + 3] = f2tf32(vv.w);
        }
        if (tid < SKT) msf[tid] = mask[b * SS + s0 + tid] ? 0.0f : -1e30f;
        __syncthreads();

        // --- scores S = Q . K^T ---
        float s[8][4];
#pragma unroll
        for (int n = 0; n < 8; n++)
#pragma unroll
            for (int f = 0; f < 4; f++) s[n][f] = 0.f;

#pragma unroll
        for (int kk = 0; kk < 8; kk++) {
            uint32_t a[4];
            ldsm4(a[0], a[1], a[2], a[3], qa + kk * 32);
#pragma unroll
            for (int p = 0; p < 4; p++) {
                uint32_t bf0[2], bf1[2];
                ldsm4(bf0[0], bf0[1], bf1[0], bf1[1],
                      ka + (uint32_t)(p * 16 * KSTR) * 4 + kk * 32);
                mma_tf32(s[2 * p],     a, bf0);
                mma_tf32(s[2 * p + 1], a, bf1);
            }
        }

        // --- mask + scale (base-2 domain), tile row max ---
        float tmax0 = -1e30f, tmax1 = -1e30f;
#pragma unroll
        for (int n = 0; n < 8; n++) {
            const float mf0 = msf[n * 8 + 2 * lr];
            const float mf1 = msf[n * 8 + 2 * lr + 1];
            s[n][0] = fmaf(s[n][0], C, mf0);
            s[n][1] = fmaf(s[n][1], C, mf1);
            s[n][2] = fmaf(s[n][2], C, mf0);
            s[n][3] = fmaf(s[n][3], C, mf1);
            tmax0 = fmaxf(tmax0, fmaxf(s[n][0], s[n][1]));
            tmax1 = fmaxf(tmax1, fmaxf(s[n][2], s[n][3]));
        }
        tmax0 = fmaxf(tmax0, __shfl_xor_sync(0xffffffffu, tmax0, 1));
        tmax0 = fmaxf(tmax0, __shfl_xor_sync(0xffffffffu, tmax0, 2));
        tmax1 = fmaxf(tmax1, __shfl_xor_sync(0xffffffffu, tmax1, 1));
        tmax1 = fmaxf(tmax1, __shfl_xor_sync(0xffffffffu, tmax1, 2));

        const float mn0 = fmaxf(m0, tmax0);
        const float mn1 = fmaxf(m1, tmax1);
        const float c0 = fexp2(m0 - mn0);
        const float c1 = fexp2(m1 - mn1);
        m0 = mn0; m1 = mn1;
        l0 *= c0;  l1 *= c1;

        // --- p = 2^(s-m): rescale O, accumulate l, stage P (tf32) ---
#pragma unroll
        for (int n = 0; n < 8; n++) {
            o[n][0] *= c0; o[n][1] *= c0; o[n][2] *= c1; o[n][3] *= c1;
            const float p0 = fexp2(s[n][0] - m0);
            const float p1 = fexp2(s[n][1] - m0);
            const float p2 = fexp2(s[n][2] - m1);
            const float p3 = fexp2(s[n][3] - m1);
            l0 += p0 + p1;
            l1 += p2 + p3;
            const int pb = (wm + lq) * PSTR + n * 8 + 2 * lr;
            Ps[pb]                = f2tf32(p0);
            Ps[pb + 1]            = f2tf32(p1);
            Ps[pb + 8 * PSTR]     = f2tf32(p2);
            Ps[pb + 8 * PSTR + 1] = f2tf32(p3);
        }
        __syncwarp();

        // --- O += P . V ---
#pragma unroll
        for (int kk = 0; kk < 8; kk++) {
            uint32_t a[4];
            ldsm4(a[0], a[1], a[2], a[3], pa + kk * 32);
#pragma unroll
            for (int n = 0; n < 8; n++) {
                uint32_t bf[2];
                bf[0] = Vs[(kk * 8 + lr) * VSTR + n * 8 + lq];
                bf[1] = Vs[(kk * 8 + lr + 4) * VSTR + n * 8 + lq];
                mma_tf32(o[n], a, bf);
            }
        }
    }

    // --- finalize ---
    l0 += __shfl_xor_sync(0xffffffffu, l0, 1);
    l0 += __shfl_xor_sync(0xffffffffu, l0, 2);
    l1 += __shfl_xor_sync(0xffffffffu, l1, 1);
    l1 += __shfl_xor_sync(0xffffffffu, l1, 2);
    const float inv0 = 1.0f / l0;
    const float inv1 = 1.0f / l1;

    float* Og = O + ((size_t)b * SS + q0 + wm + lq) * EE + h * DD;
#pragma unroll
    for (int n = 0; n < 8; n++) {
        *(float2*)&Og[n * 8 + 2 * lr] =
            make_float2(o[n][0] * inv0, o[n][1] * inv0);
        *(float2*)&Og[(size_t)8 * EE + n * 8 + 2 * lr] =
            make_float2(o[n][2] * inv1, o[n][3] * inv1);
    }
}

// ---------------------------------------------------------------------------
// Launch
// Inputs (metadata order): value, key_in, query, mask,
//                          Wq, bq, Wk, bk, Wv, bv, Wo, bo
// ---------------------------------------------------------------------------
extern "C" void kernel_launch(void* const* d_in, const int* in_sizes, int n_in,
                              void* d_out, int out_size)
{
    const float* value  = (const float*)d_in[0];
    const float* key_in = (const float*)d_in[1];
    const float* query  = (const float*)d_in[2];
    const int*   mask   = (const int*)  d_in[3];
    const float* Wq = (const float*)d_in[4];
    const float* bq = (const float*)d_in[5];
    const float* Wk = (const float*)d_in[6];
    const float* bk = (const float*)d_in[7];
    const float* Wv = (const float*)d_in[8];
    const float* bv = (const float*)d_in[9];
    const float* Wo = (const float*)d_in[10];
    const float* bo = (const float*)d_in[11];
    float* out = (float*)d_out;

    float *dQ, *dK, *dV, *dA;
    cudaGetSymbolAddress((void**)&dQ, g_Q);
    cudaGetSymbolAddress((void**)&dK, g_K);
    cudaGetSymbolAddress((void**)&dV, g_V);
    cudaGetSymbolAddress((void**)&dA, g_A);

    cudaFuncSetAttribute(gemm2_tf32,
                         cudaFuncAttributeMaxDynamicSharedMemorySize, G2_SMEM_BYTES);
    cudaFuncSetAttribute(flash_mma_kernel,
                         cudaFuncAttributeMaxDynamicSharedMemorySize, FA_SMEM_BYTES);

    const int M = BB * SS;   // 4096
    const int N = EE;        // 1024
    const int Kd = EE;       // 1024

    dim3 ggrid(N / BN2, M / BM2);   // (8, 16) = 128 CTAs

    gemm2_tf32<<<ggrid, 256, G2_SMEM_BYTES>>>(query,  Wq, bq, dQ, M, N, Kd);
    gemm2_tf32<<<ggrid, 256, G2_SMEM_BYTES>>>(key_in, Wk, bk, dK, M, N, Kd);
    gemm2_tf32<<<ggrid, 256, G2_SMEM_BYTES>>>(value,  Wv, bv, dV, M, N, Kd);

    dim3 fgrid(SS / 128, HH, BB);   // (8, 16, 4)
    flash_mma_kernel<<<fgrid, FA_THREADS, FA_SMEM_BYTES>>>(dQ, dK, dV, mask, dA);

    gemm2_tf32<<<ggrid, 256, G2_SMEM_BYTES>>>(dA, Wo, bo, out, M, N, Kd);
}

// round 9
// speedup vs baseline: 4.0229x; 1.0083x over previous
#include <cuda_runtime.h>
#include <cuda_bf16.h>
#include <cstdint>

// Problem shape (fixed): B=4, S=1024, E=1024, H=16, D=64
#define BB 4
#define SS 1024
#define EE 1024
#define HH 16
#define DD 64

// ---------------------------------------------------------------------------
// Scratch (static __device__ globals — allocation-free per harness rules)
// ---------------------------------------------------------------------------
__device__ float g_Q[BB * SS * EE];
__device__ float g_K[BB * SS * EE];
__device__ float g_V[BB * SS * EE];
__device__ float g_A[BB * SS * EE];

// ---------------------------------------------------------------------------
// Helpers
// ---------------------------------------------------------------------------
__device__ __forceinline__ uint32_t smem_u32(const void* p) {
    uint32_t a;
    asm("{ .reg .u64 t; cvta.to.shared.u64 t, %1; cvt.u32.u64 %0, t; }"
        : "=r"(a) : "l"(p));
    return a;
}

__device__ __forceinline__ uint32_t f2tf32(float f) {
    uint32_t r;
    asm("cvt.rna.tf32.f32 %0, %1;" : "=r"(r) : "f"(f));
    return r;
}

// mma.sync m16n8k8 tf32: D(f32) += A(tf32) * B(tf32)
__device__ __forceinline__ void mma_tf32(float* c, const uint32_t* a, const uint32_t* b) {
    asm volatile(
        "mma.sync.aligned.m16n8k8.row.col.f32.tf32.tf32.f32 "
        "{%0,%1,%2,%3}, {%4,%5,%6,%7}, {%8,%9}, {%0,%1,%2,%3};"
        : "+f"(c[0]), "+f"(c[1]), "+f"(c[2]), "+f"(c[3])
        : "r"(a[0]), "r"(a[1]), "r"(a[2]), "r"(a[3]),
          "r"(b[0]), "r"(b[1]));
}

// ldmatrix x4 (non-trans). Within each matrix, lane l gets (row l>>2, f32col l&3).
__device__ __forceinline__ void ldsm4(uint32_t& r0, uint32_t& r1,
                                      uint32_t& r2, uint32_t& r3, uint32_t addr) {
    asm volatile(
        "ldmatrix.sync.aligned.m8n8.x4.shared.b16 {%0,%1,%2,%3}, [%4];"
        : "=r"(r0), "=r"(r1), "=r"(r2), "=r"(r3) : "r"(addr));
}

__device__ __forceinline__ void cp16(uint32_t dst, const void* src) {
    asm volatile("cp.async.cg.shared.global [%0], [%1], 16;"
                 :: "r"(dst), "l"(src));
}
__device__ __forceinline__ void cp_commit() {
    asm volatile("cp.async.commit_group;");
}
__device__ __forceinline__ void cp_wait0() {
    asm volatile("cp.async.wait_group 0;" ::: "memory");
}
__device__ __forceinline__ void cp_wait1() {
    asm volatile("cp.async.wait_group 1;" ::: "memory");
}

// FMA-pipe exp2 for x <= 0 (clamped at -126). ~4e-5 abs err.
__device__ __forceinline__ float fexp2(float x) {
    x = fmaxf(x, -126.0f);
    float z = x + 12582912.0f;
    int   i = __float_as_int(z);
    float f = x - (z - 12582912.0f);
    float p = 9.6181e-3f;
    p = fmaf(p, f, 5.55041e-2f);
    p = fmaf(p, f, 2.402265e-1f);
    p = fmaf(p, f, 6.931472e-1f);
    p = fmaf(p, f, 1.0f);
    return __int_as_float(__float_as_int(p) + (i << 23));
}

// ---------------------------------------------------------------------------
// GEMM v3:  Y[M,N] = X[M,K] @ W[N,K]^T + bias[N]
// CTA 256x128, 8 warps (4m x 2n) of 64x64. BK=32. cp.async TRIPLE buffer.
// Raw fp32 in smem (stride 36); cvt->tf32 at fragment load via ldmatrix.
// ---------------------------------------------------------------------------
#define BM2 256
#define BN2 128
#define BK2 32
#define LD2 36

#define G2_ABUF (BM2 * LD2)                    // 9216 u32
#define G2_BBUF (BN2 * LD2)                    // 4608 u32
#define G2_STAGE (G2_ABUF + G2_BBUF)           // 13824 u32
#define G2_SMEM_BYTES (3 * G2_STAGE * 4)       // 165888 B

__global__ __launch_bounds__(256) void gemm2_tf32(
    const float* __restrict__ X, const float* __restrict__ W,
    const float* __restrict__ bias, float* __restrict__ Y,
    int M, int N, int K)
{
    extern __shared__ uint32_t smg[];
    const uint32_t sb = smem_u32(smg);

    const int tid = threadIdx.x;
    const int wid = tid >> 5;
    const int lane = tid & 31;
    const int lq = lane >> 2;
    const int lr = lane & 3;

    const int wm = (wid >> 1) * 64;     // 0,64,128,192
    const int wn = (wid & 1) * 64;      // 0,64

    const int row0 = blockIdx.y * BM2;
    const int col0 = blockIdx.x * BN2;

    float c[4][8][4];
#pragma unroll
    for (int m = 0; m < 4; m++)
#pragma unroll
        for (int n = 0; n < 8; n++)
#pragma unroll
            for (int f = 0; f < 4; f++) c[m][n][f] = 0.f;

    // loader mapping
    const int lrow = tid >> 3;          // 0..31
    const int lc4  = (tid & 7) * 4;     // 0..28

    // ldmatrix lane address components
    const int aRow = wm + (lane & 15);
    const int aCol = (lane >> 4) * 4;
    const int bRow = wn + ((lane >> 4) << 3) + (lane & 7);
    const int bCol = ((lane >> 3) & 1) * 4;

    const int nstages = K / BK2;        // 32

    // prologue: stages 0 and 1
#pragma unroll
    for (int ps = 0; ps < 2; ps++) {
        const int k0 = ps * BK2;
        const uint32_t ab = sb + (uint32_t)(ps * G2_STAGE) * 4;
#pragma unroll
        for (int i = 0; i < 8; i++) {
            const int r = lrow + i * 32;
            cp16(ab + (uint32_t)(r * LD2 + lc4) * 4,
                 &X[(size_t)(row0 + r) * K + k0 + lc4]);
        }
#pragma unroll
        for (int i = 0; i < 4; i++) {
            const int r = lrow + i * 32;
            cp16(ab + (uint32_t)(G2_ABUF + r * LD2 + lc4) * 4,
                 &W[(size_t)(col0 + r) * K + k0 + lc4]);
        }
        cp_commit();
    }

    int cur = 0;   // s % 3
    int nx2 = 2;   // (s+2) % 3
#pragma unroll 1
    for (int s = 0; s < nstages; s++) {
        if (s == nstages - 1) cp_wait0(); else cp_wait1();
        __syncthreads();

        if (s + 2 < nstages) {
            const int k0 = (s + 2) * BK2;
            const uint32_t ab = sb + (uint32_t)(nx2 * G2_STAGE) * 4;
#pragma unroll
            for (int i = 0; i < 8; i++) {
                const int r = lrow + i * 32;
                cp16(ab + (uint32_t)(r * LD2 + lc4) * 4,
                     &X[(size_t)(row0 + r) * K + k0 + lc4]);
            }
#pragma unroll
            for (int i = 0; i < 4; i++) {
                const int r = lrow + i * 32;
                cp16(ab + (uint32_t)(G2_ABUF + r * LD2 + lc4) * 4,
                     &W[(size_t)(col0 + r) * K + k0 + lc4]);
            }
            cp_commit();
        }

        const uint32_t abase = sb + (uint32_t)(cur * G2_STAGE) * 4;
        const uint32_t bbase = abase + (uint32_t)G2_ABUF * 4;

#pragma unroll
        for (int kk = 0; kk < 4; kk++) {
            const int k8 = kk * 8;
            uint32_t a[4][4], bf[8][2];
#pragma unroll
            for (int m = 0; m < 4; m++) {
                uint32_t r0, r1, r2, r3;
                ldsm4(r0, r1, r2, r3,
                      abase + (uint32_t)((aRow + m * 16) * LD2 + k8 + aCol) * 4);
                a[m][0] = f2tf32(__uint_as_float(r0));
                a[m][1] = f2tf32(__uint_as_float(r1));
                a[m][2] = f2tf32(__uint_as_float(r2));
                a[m][3] = f2tf32(__uint_as_float(r3));
            }
#pragma unroll
            for (int p = 0; p < 4; p++) {
                uint32_t r0, r1, r2, r3;
                ldsm4(r0, r1, r2, r3,
                      bbase + (uint32_t)((bRow + p * 16) * LD2 + k8 + bCol) * 4);
                bf[2 * p][0]     = f2tf32(__uint_as_float(r0));
                bf[2 * p][1]     = f2tf32(__uint_as_float(r1));
                bf[2 * p + 1][0] = f2tf32(__uint_as_float(r2));
                bf[2 * p + 1][1] = f2tf32(__uint_as_float(r3));
            }
#pragma unroll
            for (int m = 0; m < 4; m++)
#pragma unroll
                for (int n = 0; n < 8; n++)
                    mma_tf32(c[m][n], a[m], bf[n]);
        }

        cur = (cur == 2) ? 0 : cur + 1;
        nx2 = (nx2 == 2) ? 0 : nx2 + 1;
    }

    // epilogue: fused bias
#pragma unroll
    for (int m = 0; m < 4; m++) {
        const int r_lo = row0 + wm + m * 16 + lq;
        const int r_hi = r_lo + 8;
#pragma unroll
        for (int n = 0; n < 8; n++) {
            const int col = col0 + wn + n * 8 + lr * 2;
            const float b0 = bias[col];
            const float b1 = bias[col + 1];
            *(float2*)&Y[(size_t)r_lo * N + col] =
                make_float2(c[m][n][0] + b0, c[m][n][1] + b1);
            *(float2*)&Y[(size_t)r_hi * N + col] =
                make_float2(c[m][n][2] + b0, c[m][n][3] + b1);
        }
    }
}

// ---------------------------------------------------------------------------
// Tensor-core flash attention v2.
// Q/K/P fragments via ldmatrix (stride 68, uint4 STS loaders).
// V stored TRANSPOSED Vt[d][key] with XOR swizzle -> ldmatrix for PV B-frags.
//   u32 index: vt_idx(d,key) = d*64 + (((key>>2) ^ (d&7) ^ ((d>>3)&7))*4 + (key&3))
//   LDSM conflict-free; transpose STS 2-way (same as R8's scalar path).
// ---------------------------------------------------------------------------
#define FA_THREADS 256
#define SKT 64
#define QSTR 68
#define KSTR 68
#define PSTR 68

#define OFF_Q 0
#define OFF_K (128 * QSTR)                    // 8704
#define OFF_V (OFF_K + 64 * KSTR)             // 13056
#define OFF_P (OFF_V + 64 * 64)               // 17152
#define OFF_M (OFF_P + 128 * PSTR)            // 25856
#define FA_SMEM_U32 (OFF_M + 64)              // 25920
#define FA_SMEM_BYTES (FA_SMEM_U32 * 4)       // 103680

__device__ __forceinline__ int vt_idx(int d, int key) {
    int grp = (key >> 2) ^ (d & 7) ^ ((d >> 3) & 7);
    return d * 64 + grp * 4 + (key & 3);
}

__global__ __launch_bounds__(FA_THREADS) void flash_mma_kernel(
    const float* __restrict__ Q, const float* __restrict__ K,
    const float* __restrict__ V, const int* __restrict__ mask,
    float* __restrict__ O)
{
    extern __shared__ uint32_t sm[];
    uint32_t* Qs = sm + OFF_Q;
    uint32_t* Ks = sm + OFF_K;
    uint32_t* Vs = sm + OFF_V;
    uint32_t* Ps = sm + OFF_P;
    float*   msf = (float*)(sm + OFF_M);
    const uint32_t sb = smem_u32(sm);

    const int b  = blockIdx.z;
    const int h  = blockIdx.y;
    const int q0 = blockIdx.x * 128;
    const int tid = threadIdx.x;
    const int wid = tid >> 5;
    const int lane = tid & 31;
    const int lq = lane >> 2;
    const int lr = lane & 3;
    const int wm = wid * 16;

    const float C = 0.0450842200f;   // log2(e) / 32

    // ldmatrix lane addresses (byte units)
    const uint32_t qa = sb + (uint32_t)(OFF_Q + (wm + (lane & 15)) * QSTR
                                        + ((lane >> 4) << 2)) * 4;
    const uint32_t ka = sb + (uint32_t)(OFF_K + (((lane >> 4) << 3) + (lane & 7)) * KSTR
                                        + (((lane >> 3) & 1) << 2)) * 4;
    const uint32_t pa = sb + (uint32_t)(OFF_P + (wm + (lane & 15)) * PSTR
                                        + ((lane >> 4) << 2)) * 4;
    // V ldmatrix components: lane supplies row d = 16p + dl, granule 2kk+half
    const int jj   = lane & 7;
    const int half = (lane >> 3) & 1;
    const int hv   = lane >> 4;              // 0/1
    const int dl   = 8 * hv + jj;
    const uint32_t vtb = sb + (uint32_t)OFF_V * 4 + (uint32_t)dl * 256;

    // --- load Q tile (tf32, uint4 STS) ---
    const float* Qg = Q + ((size_t)b * SS + q0) * EE + h * DD;
#pragma unroll
    for (int it = 0; it < 8; it++) {
        int idx = tid + it * 256;
        int r = idx >> 4, c4 = (idx & 15) * 4;
        float4 v = *(const float4*)&Qg[(size_t)r * EE + c4];
        uint4 t;
        t.x = f2tf32(v.x); t.y = f2tf32(v.y); t.z = f2tf32(v.z); t.w = f2tf32(v.w);
        *(uint4*)&Qs[r * QSTR + c4] = t;
    }

    float o[8][4];
#pragma unroll
    for (int n = 0; n < 8; n++)
#pragma unroll
        for (int f = 0; f < 4; f++) o[n][f] = 0.f;

    float m0 = -1e30f, m1 = -1e30f, l0 = 0.f, l1 = 0.f;

    const float* Kg = K + (size_t)b * SS * EE + h * DD;
    const float* Vg = V + (size_t)b * SS * EE + h * DD;

    for (int s0 = 0; s0 < SS; s0 += SKT) {
        __syncthreads();
#pragma unroll
        for (int it = 0; it < 4; it++) {
            int idx = tid + it * 256;
            int r = idx >> 4, c4 = (idx & 15) * 4;
            float4 kv = *(const float4*)&Kg[(size_t)(s0 + r) * EE + c4];
            float4 vv = *(const float4*)&Vg[(size_t)(s0 + r) * EE + c4];
            uint4 tk;
            tk.x = f2tf32(kv.x); tk.y = f2tf32(kv.y);
            tk.z = f2tf32(kv.z); tk.w = f2tf32(kv.w);
            *(uint4*)&Ks[r * KSTR + c4] = tk;
            // V transpose into swizzled Vt[d][key]
            Vs[vt_idx(c4 + 0, r)] = f2tf32(vv.x);
            Vs[vt_idx(c4 + 1, r)] = f2tf32(vv.y);
            Vs[vt_idx(c4 + 2, r)] = f2tf32(vv.z);
            Vs[vt_idx(c4 + 3, r)] = f2tf32(vv.w);
        }
        if (tid < SKT) msf[tid] = mask[b * SS + s0 + tid] ? 0.0f : -1e30f;
        __syncthreads();

        // --- scores S = Q . K^T ---
        float s[8][4];
#pragma unroll
        for (int n = 0; n < 8; n++)
#pragma unroll
            for (int f = 0; f < 4; f++) s[n][f] = 0.f;

#pragma unroll
        for (int kk = 0; kk < 8; kk++) {
            uint32_t a[4];
            ldsm4(a[0], a[1], a[2], a[3], qa + kk * 32);
#pragma unroll
            for (int p = 0; p < 4; p++) {
                uint32_t bf0[2], bf1[2];
                ldsm4(bf0[0], bf0[1], bf1[0], bf1[1],
                      ka + (uint32_t)(p * 16 * KSTR) * 4 + kk * 32);
                mma_tf32(s[2 * p],     a, bf0);
                mma_tf32(s[2 * p + 1], a, bf1);
            }
        }

        // --- mask + scale (base-2 domain), tile row max ---
        float tmax0 = -1e30f, tmax1 = -1e30f;
#pragma unroll
        for (int n = 0; n < 8; n++) {
            const float mf0 = msf[n * 8 + 2 * lr];
            const float mf1 = msf[n * 8 + 2 * lr + 1];
            s[n][0] = fmaf(s[n][0], C, mf0);
            s[n][1] = fmaf(s[n][1], C, mf1);
            s[n][2] = fmaf(s[n][2], C, mf0);
            s[n][3] = fmaf(s[n][3], C, mf1);
            tmax0 = fmaxf(tmax0, fmaxf(s[n][0], s[n][1]));
            tmax1 = fmaxf(tmax1, fmaxf(s[n][2], s[n][3]));
        }
        tmax0 = fmaxf(tmax0, __shfl_xor_sync(0xffffffffu, tmax0, 1));
        tmax0 = fmaxf(tmax0, __shfl_xor_sync(0xffffffffu, tmax0, 2));
        tmax1 = fmaxf(tmax1, __shfl_xor_sync(0xffffffffu, tmax1, 1));
        tmax1 = fmaxf(tmax1, __shfl_xor_sync(0xffffffffu, tmax1, 2));

        const float mn0 = fmaxf(m0, tmax0);
        const float mn1 = fmaxf(m1, tmax1);
        const float c0 = fexp2(m0 - mn0);
        const float c1 = fexp2(m1 - mn1);
        m0 = mn0; m1 = mn1;
        l0 *= c0;  l1 *= c1;

        // --- p = 2^(s-m): rescale O, accumulate l, stage P (tf32) ---
#pragma unroll
        for (int n = 0; n < 8; n++) {
            o[n][0] *= c0; o[n][1] *= c0; o[n][2] *= c1; o[n][3] *= c1;
            const float p0 = fexp2(s[n][0] - m0);
            const float p1 = fexp2(s[n][1] - m0);
            const float p2 = fexp2(s[n][2] - m1);
            const float p3 = fexp2(s[n][3] - m1);
            l0 += p0 + p1;
            l1 += p2 + p3;
            const int pb = (wm + lq) * PSTR + n * 8 + 2 * lr;
            Ps[pb]                = f2tf32(p0);
            Ps[pb + 1]            = f2tf32(p1);
            Ps[pb + 8 * PSTR]     = f2tf32(p2);
            Ps[pb + 8 * PSTR + 1] = f2tf32(p3);
        }
        __syncwarp();

        // --- O += P . V  (V via swizzled ldmatrix) ---
#pragma unroll
        for (int kk = 0; kk < 8; kk++) {
            uint32_t a[4];
            ldsm4(a[0], a[1], a[2], a[3], pa + kk * 32);
#pragma unroll
            for (int p = 0; p < 4; p++) {
                // group = (2kk+half) ^ jj ^ (2p+hv);  addr = vtb + p*4096 + grp*16
                const int grp = (2 * kk + half) ^ jj ^ (2 * p + hv);
                uint32_t bf0[2], bf1[2];
                ldsm4(bf0[0], bf0[1], bf1[0], bf1[1],
                      vtb + (uint32_t)(p * 4096) + (uint32_t)(grp * 16));
                mma_tf32(o[2 * p],     a, bf0);
                mma_tf32(o[2 * p + 1], a, bf1);
            }
        }
    }

    // --- finalize ---
    l0 += __shfl_xor_sync(0xffffffffu, l0, 1);
    l0 += __shfl_xor_sync(0xffffffffu, l0, 2);
    l1 += __shfl_xor_sync(0xffffffffu, l1, 1);
    l1 += __shfl_xor_sync(0xffffffffu, l1, 2);
    const float inv0 = 1.0f / l0;
    const float inv1 = 1.0f / l1;

    float* Og = O + ((size_t)b * SS + q0 + wm + lq) * EE + h * DD;
#pragma unroll
    for (int n = 0; n < 8; n++) {
        *(float2*)&Og[n * 8 + 2 * lr] =
            make_float2(o[n][0] * inv0, o[n][1] * inv0);
        *(float2*)&Og[(size_t)8 * EE + n * 8 + 2 * lr] =
            make_float2(o[n][2] * inv1, o[n][3] * inv1);
    }
}

// ---------------------------------------------------------------------------
// Launch
// Inputs (metadata order): value, key_in, query, mask,
//                          Wq, bq, Wk, bk, Wv, bv, Wo, bo
// ---------------------------------------------------------------------------
extern "C" void kernel_launch(void* const* d_in, const int* in_sizes, int n_in,
                              void* d_out, int out_size)
{
    const float* value  = (const float*)d_in[0];
    const float* key_in = (const float*)d_in[1];
    const float* query  = (const float*)d_in[2];
    const int*   mask   = (const int*)  d_in[3];
    const float* Wq = (const float*)d_in[4];
    const float* bq = (const float*)d_in[5];
    const float* Wk = (const float*)d_in[6];
    const float* bk = (const float*)d_in[7];
    const float* Wv = (const float*)d_in[8];
    const float* bv = (const float*)d_in[9];
    const float* Wo = (const float*)d_in[10];
    const float* bo = (const float*)d_in[11];
    float* out = (float*)d_out;

    float *dQ, *dK, *dV, *dA;
    cudaGetSymbolAddress((void**)&dQ, g_Q);
    cudaGetSymbolAddress((void**)&dK, g_K);
    cudaGetSymbolAddress((void**)&dV, g_V);
    cudaGetSymbolAddress((void**)&dA, g_A);

    cudaFuncSetAttribute(gemm2_tf32,
                         cudaFuncAttributeMaxDynamicSharedMemorySize, G2_SMEM_BYTES);
    cudaFuncSetAttribute(flash_mma_kernel,
                         cudaFuncAttributeMaxDynamicSharedMemorySize, FA_SMEM_BYTES);

    const int M = BB * SS;   // 4096
    const int N = EE;        // 1024
    const int Kd = EE;       // 1024

    dim3 ggrid(N / BN2, M / BM2);   // (8, 16) = 128 CTAs

    gemm2_tf32<<<ggrid, 256, G2_SMEM_BYTES>>>(query,  Wq, bq, dQ, M, N, Kd);
    gemm2_tf32<<<ggrid, 256, G2_SMEM_BYTES>>>(key_in, Wk, bk, dK, M, N, Kd);
    gemm2_tf32<<<ggrid, 256, G2_SMEM_BYTES>>>(value,  Wv, bv, dV, M, N, Kd);

    dim3 fgrid(SS / 128, HH, BB);   // (8, 16, 4)
    flash_mma_kernel<<<fgrid, FA_THREADS, FA_SMEM_BYTES>>>(dQ, dK, dV, mask, dA);

    gemm2_tf32<<<ggrid, 256, G2_SMEM_BYTES>>>(dA, Wo, bo, out, M, N, Kd);
}

// round 11
// speedup vs baseline: 4.0869x; 1.0159x over previous
#include <cuda_runtime.h>
#include <cuda_bf16.h>
#include <cstdint>

// Problem shape (fixed): B=4, S=1024, E=1024, H=16, D=64
#define BB 4
#define SS 1024
#define EE 1024
#define HH 16
#define DD 64

// ---------------------------------------------------------------------------
// Scratch (static __device__ globals — allocation-free per harness rules)
// ---------------------------------------------------------------------------
__device__ float g_Q[BB * SS * EE];
__device__ float g_K[BB * SS * EE];
__device__ float g_V[BB * SS * EE];
__device__ float g_A[BB * SS * EE];

// ---------------------------------------------------------------------------
// Helpers
// ---------------------------------------------------------------------------
__device__ __forceinline__ uint32_t smem_u32(const void* p) {
    uint32_t a;
    asm("{ .reg .u64 t; cvta.to.shared.u64 t, %1; cvt.u32.u64 %0, t; }"
        : "=r"(a) : "l"(p));
    return a;
}

__device__ __forceinline__ uint32_t f2tf32(float f) {
    uint32_t r;
    asm("cvt.rna.tf32.f32 %0, %1;" : "=r"(r) : "f"(f));
    return r;
}

// mma.sync m16n8k8 tf32: D(f32) += A(tf32) * B(tf32)
__device__ __forceinline__ void mma_tf32(float* c, const uint32_t* a, const uint32_t* b) {
    asm volatile(
        "mma.sync.aligned.m16n8k8.row.col.f32.tf32.tf32.f32 "
        "{%0,%1,%2,%3}, {%4,%5,%6,%7}, {%8,%9}, {%0,%1,%2,%3};"
        : "+f"(c[0]), "+f"(c[1]), "+f"(c[2]), "+f"(c[3])
        : "r"(a[0]), "r"(a[1]), "r"(a[2]), "r"(a[3]),
          "r"(b[0]), "r"(b[1]));
}

// ldmatrix x4 (non-trans). Within each matrix, lane l gets (row l>>2, f32col l&3).
__device__ __forceinline__ void ldsm4(uint32_t& r0, uint32_t& r1,
                                      uint32_t& r2, uint32_t& r3, uint32_t addr) {
    asm volatile(
        "ldmatrix.sync.aligned.m8n8.x4.shared.b16 {%0,%1,%2,%3}, [%4];"
        : "=r"(r0), "=r"(r1), "=r"(r2), "=r"(r3) : "r"(addr));
}

__device__ __forceinline__ void cp16(uint32_t dst, const void* src) {
    asm volatile("cp.async.cg.shared.global [%0], [%1], 16;"
                 :: "r"(dst), "l"(src));
}
__device__ __forceinline__ void cp_commit() {
    asm volatile("cp.async.commit_group;");
}
__device__ __forceinline__ void cp_wait0() {
    asm volatile("cp.async.wait_group 0;" ::: "memory");
}
__device__ __forceinline__ void cp_wait1() {
    asm volatile("cp.async.wait_group 1;" ::: "memory");
}

// FMA-pipe exp2 for x <= 0 (clamped at -126). ~4e-5 abs err.
__device__ __forceinline__ float fexp2(float x) {
    x = fmaxf(x, -126.0f);
    float z = x + 12582912.0f;
    int   i = __float_as_int(z);
    float f = x - (z - 12582912.0f);
    float p = 9.6181e-3f;
    p = fmaf(p, f, 5.55041e-2f);
    p = fmaf(p, f, 2.402265e-1f);
    p = fmaf(p, f, 6.931472e-1f);
    p = fmaf(p, f, 1.0f);
    return __int_as_float(__float_as_int(p) + (i << 23));
}

// ---------------------------------------------------------------------------
// GEMM v3 (unchanged from R9):  Y = X @ W^T + bias.  CTA 256x128, triple buf.
// ---------------------------------------------------------------------------
#define BM2 256
#define BN2 128
#define BK2 32
#define LD2 36

#define G2_ABUF (BM2 * LD2)
#define G2_BBUF (BN2 * LD2)
#define G2_STAGE (G2_ABUF + G2_BBUF)
#define G2_SMEM_BYTES (3 * G2_STAGE * 4)

__global__ __launch_bounds__(256) void gemm2_tf32(
    const float* __restrict__ X, const float* __restrict__ W,
    const float* __restrict__ bias, float* __restrict__ Y,
    int M, int N, int K)
{
    extern __shared__ uint32_t smg[];
    const uint32_t sb = smem_u32(smg);

    const int tid = threadIdx.x;
    const int wid = tid >> 5;
    const int lane = tid & 31;
    const int lq = lane >> 2;
    const int lr = lane & 3;

    const int wm = (wid >> 1) * 64;
    const int wn = (wid & 1) * 64;

    const int row0 = blockIdx.y * BM2;
    const int col0 = blockIdx.x * BN2;

    float c[4][8][4];
#pragma unroll
    for (int m = 0; m < 4; m++)
#pragma unroll
        for (int n = 0; n < 8; n++)
#pragma unroll
            for (int f = 0; f < 4; f++) c[m][n][f] = 0.f;

    const int lrow = tid >> 3;
    const int lc4  = (tid & 7) * 4;

    const int aRow = wm + (lane & 15);
    const int aCol = (lane >> 4) * 4;
    const int bRow = wn + ((lane >> 4) << 3) + (lane & 7);
    const int bCol = ((lane >> 3) & 1) * 4;

    const int nstages = K / BK2;

#pragma unroll
    for (int ps = 0; ps < 2; ps++) {
        const int k0 = ps * BK2;
        const uint32_t ab = sb + (uint32_t)(ps * G2_STAGE) * 4;
#pragma unroll
        for (int i = 0; i < 8; i++) {
            const int r = lrow + i * 32;
            cp16(ab + (uint32_t)(r * LD2 + lc4) * 4,
                 &X[(size_t)(row0 + r) * K + k0 + lc4]);
        }
#pragma unroll
        for (int i = 0; i < 4; i++) {
            const int r = lrow + i * 32;
            cp16(ab + (uint32_t)(G2_ABUF + r * LD2 + lc4) * 4,
                 &W[(size_t)(col0 + r) * K + k0 + lc4]);
        }
        cp_commit();
    }

    int cur = 0;
    int nx2 = 2;
#pragma unroll 1
    for (int s = 0; s < nstages; s++) {
        if (s == nstages - 1) cp_wait0(); else cp_wait1();
        __syncthreads();

        if (s + 2 < nstages) {
            const int k0 = (s + 2) * BK2;
            const uint32_t ab = sb + (uint32_t)(nx2 * G2_STAGE) * 4;
#pragma unroll
            for (int i = 0; i < 8; i++) {
                const int r = lrow + i * 32;
                cp16(ab + (uint32_t)(r * LD2 + lc4) * 4,
                     &X[(size_t)(row0 + r) * K + k0 + lc4]);
            }
#pragma unroll
            for (int i = 0; i < 4; i++) {
                const int r = lrow + i * 32;
                cp16(ab + (uint32_t)(G2_ABUF + r * LD2 + lc4) * 4,
                     &W[(size_t)(col0 + r) * K + k0 + lc4]);
            }
            cp_commit();
        }

        const uint32_t abase = sb + (uint32_t)(cur * G2_STAGE) * 4;
        const uint32_t bbase = abase + (uint32_t)G2_ABUF * 4;

#pragma unroll
        for (int kk = 0; kk < 4; kk++) {
            const int k8 = kk * 8;
            uint32_t a[4][4], bf[8][2];
#pragma unroll
            for (int m = 0; m < 4; m++) {
                uint32_t r0, r1, r2, r3;
                ldsm4(r0, r1, r2, r3,
                      abase + (uint32_t)((aRow + m * 16) * LD2 + k8 + aCol) * 4);
                a[m][0] = f2tf32(__uint_as_float(r0));
                a[m][1] = f2tf32(__uint_as_float(r1));
                a[m][2] = f2tf32(__uint_as_float(r2));
                a[m][3] = f2tf32(__uint_as_float(r3));
            }
#pragma unroll
            for (int p = 0; p < 4; p++) {
                uint32_t r0, r1, r2, r3;
                ldsm4(r0, r1, r2, r3,
                      bbase + (uint32_t)((bRow + p * 16) * LD2 + k8 + bCol) * 4);
                bf[2 * p][0]     = f2tf32(__uint_as_float(r0));
                bf[2 * p][1]     = f2tf32(__uint_as_float(r1));
                bf[2 * p + 1][0] = f2tf32(__uint_as_float(r2));
                bf[2 * p + 1][1] = f2tf32(__uint_as_float(r3));
            }
#pragma unroll
            for (int m = 0; m < 4; m++)
#pragma unroll
                for (int n = 0; n < 8; n++)
                    mma_tf32(c[m][n], a[m], bf[n]);
        }

        cur = (cur == 2) ? 0 : cur + 1;
        nx2 = (nx2 == 2) ? 0 : nx2 + 1;
    }

#pragma unroll
    for (int m = 0; m < 4; m++) {
        const int r_lo = row0 + wm + m * 16 + lq;
        const int r_hi = r_lo + 8;
#pragma unroll
        for (int n = 0; n < 8; n++) {
            const int col = col0 + wn + n * 8 + lr * 2;
            const float b0 = bias[col];
            const float b1 = bias[col + 1];
            *(float2*)&Y[(size_t)r_lo * N + col] =
                make_float2(c[m][n][0] + b0, c[m][n][1] + b1);
            *(float2*)&Y[(size_t)r_hi * N + col] =
                make_float2(c[m][n][2] + b0, c[m][n][3] + b1);
        }
    }
}

// ---------------------------------------------------------------------------
// Flash attention v3.
// - P staging ELIMINATED: PV A-fragment comes straight from softmax registers
//   {s0,s2,s1,s3}; V^T stored with per-slab key permutation
//   key' = (r&~7)|((r&1)<<2)|((r>>1)&3) so the C->A fragment identity holds.
// - K + mask loaded via cp.async (double-buffered, raw fp32), K converted to
//   tf32 in-place in the loader phase.
// - V: sync LDG -> cvt -> permuted/swizzled transpose STS (as R9).
// ---------------------------------------------------------------------------
#define FA_THREADS 256
#define SKT 64
#define QSTR 68
#define KSTR 68

#define OFF_Q  0                         // 128*68 = 8704
#define OFF_K0 8704                      // 64*68 = 4352
#define OFF_K1 13056                     // 64*68 = 4352
#define OFF_VT 17408                     // 64*64 = 4096
#define OFF_MR 21504                     // 2*64 raw mask ints
#define OFF_MS 21632                     // 64 msf floats
#define FA_SMEM_U32 21696
#define FA_SMEM_BYTES (FA_SMEM_U32 * 4)  // 86784

__device__ __forceinline__ int vt_idx(int d, int key) {
    int grp = (key >> 2) ^ (d & 7) ^ ((d >> 3) & 7);
    return d * 64 + grp * 4 + (key & 3);
}

__global__ __launch_bounds__(FA_THREADS, 2) void flash_mma_kernel(
    const float* __restrict__ Q, const float* __restrict__ K,
    const float* __restrict__ V, const int* __restrict__ mask,
    float* __restrict__ O)
{
    extern __shared__ uint32_t sm[];
    uint32_t* Qs = sm + OFF_Q;
    uint32_t* Vs = sm + OFF_VT;
    const int* mraw = (const int*)(sm + OFF_MR);
    float*   msf = (float*)(sm + OFF_MS);
    const uint32_t sb = smem_u32(sm);

    const int b  = blockIdx.z;
    const int h  = blockIdx.y;
    const int q0 = blockIdx.x * 128;
    const int tid = threadIdx.x;
    const int wid = tid >> 5;
    const int lane = tid & 31;
    const int lq = lane >> 2;
    const int lr = lane & 3;
    const int wm = wid * 16;

    const float C = 0.0450842200f;   // log2(e) / 32

    // ldmatrix lane address components
    const uint32_t qa = sb + (uint32_t)(OFF_Q + (wm + (lane & 15)) * QSTR
                                        + ((lane >> 4) << 2)) * 4;
    const int krow = ((lane >> 4) << 3) + (lane & 7);
    const int kcol = ((lane >> 3) & 1) << 2;
    // V ldmatrix components
    const int jj   = lane & 7;
    const int half = (lane >> 3) & 1;
    const int hv   = lane >> 4;
    const int dl   = 8 * hv + jj;
    const uint32_t vtb = sb + (uint32_t)OFF_VT * 4 + (uint32_t)dl * 256;

    // loader mapping (shared by cp.async and transpose phases)
    // idx = tid + it*256 ; r = idx>>4 (0..63), c4 = (idx&15)*4 (0..60)

    // --- load Q tile (tf32, uint4 STS) ---
    const float* Qg = Q + ((size_t)b * SS + q0) * EE + h * DD;
#pragma unroll
    for (int it = 0; it < 8; it++) {
        int idx = tid + it * 256;
        int r = idx >> 4, c4 = (idx & 15) * 4;
        float4 v = *(const float4*)&Qg[(size_t)r * EE + c4];
        uint4 t;
        t.x = f2tf32(v.x); t.y = f2tf32(v.y); t.z = f2tf32(v.z); t.w = f2tf32(v.w);
        *(uint4*)&Qs[r * QSTR + c4] = t;
    }

    float o[8][4];
#pragma unroll
    for (int n = 0; n < 8; n++)
#pragma unroll
        for (int f = 0; f < 4; f++) o[n][f] = 0.f;

    float m0 = -1e30f, m1 = -1e30f, l0 = 0.f, l1 = 0.f;

    const float* Kg = K + (size_t)b * SS * EE + h * DD;
    const float* Vg = V + (size_t)b * SS * EE + h * DD;

    // prologue: cp.async stage 0 (K tile 0 + mask 0)
    {
#pragma unroll
        for (int it = 0; it < 4; it++) {
            int idx = tid + it * 256;
            int r = idx >> 4, c4 = (idx & 15) * 4;
            cp16(sb + (uint32_t)(OFF_K0 + r * KSTR + c4) * 4,
                 &Kg[(size_t)r * EE + c4]);
        }
        if (tid < 16)
            cp16(sb + (uint32_t)(OFF_MR + tid * 4) * 4,
                 &mask[b * SS + tid * 4]);
        cp_commit();
    }

#pragma unroll 1
    for (int t = 0; t < SS / SKT; t++) {
        const int s0 = t * SKT;
        // prefetch next tile's K + mask
        if (t + 1 < SS / SKT) {
            const uint32_t kb = ((t + 1) & 1) ? OFF_K1 : OFF_K0;
#pragma unroll
            for (int it = 0; it < 4; it++) {
                int idx = tid + it * 256;
                int r = idx >> 4, c4 = (idx & 15) * 4;
                cp16(sb + (uint32_t)(kb + r * KSTR + c4) * 4,
                     &Kg[(size_t)(s0 + SKT + r) * EE + c4]);
            }
            if (tid < 16)
                cp16(sb + (uint32_t)(OFF_MR + ((t + 1) & 1) * 64 + tid * 4) * 4,
                     &mask[b * SS + s0 + SKT + tid * 4]);
            cp_commit();
        }
        if (t == SS / SKT - 1) cp_wait0(); else cp_wait1();
        __syncthreads();   // K raw visible; prev-tile Vt/msf reads done

        // --- loader: K in-place cvt, V transpose (permuted), msf ---
        const uint32_t kb = (t & 1) ? OFF_K1 : OFF_K0;
#pragma unroll
        for (int it = 0; it < 4; it++) {
            int idx = tid + it * 256;
            int r = idx >> 4, c4 = (idx & 15) * 4;
            uint4 kv = *(uint4*)&sm[kb + r * KSTR + c4];
            kv.x = f2tf32(__uint_as_float(kv.x));
            kv.y = f2tf32(__uint_as_float(kv.y));
            kv.z = f2tf32(__uint_as_float(kv.z));
            kv.w = f2tf32(__uint_as_float(kv.w));
            *(uint4*)&sm[kb + r * KSTR + c4] = kv;

            float4 vv = *(const float4*)&Vg[(size_t)(s0 + r) * EE + c4];
            // permuted storage key: slab-local w=r&7 -> slot 4*(w&1) + (w>>1)
            const int kp = (r & ~7) | ((r & 1) << 2) | ((r >> 1) & 3);
            Vs[vt_idx(c4 + 0, kp)] = f2tf32(vv.x);
            Vs[vt_idx(c4 + 1, kp)] = f2tf32(vv.y);
            Vs[vt_idx(c4 + 2, kp)] = f2tf32(vv.z);
            Vs[vt_idx(c4 + 3, kp)] = f2tf32(vv.w);
        }
        if (tid < SKT) msf[tid] = mraw[(t & 1) * 64 + tid] ? 0.0f : -1e30f;
        __syncthreads();

        // --- scores S = Q . K^T ---
        const uint32_t ka = sb + (uint32_t)(kb + krow * KSTR + kcol) * 4;
        float s[8][4];
#pragma unroll
        for (int n = 0; n < 8; n++)
#pragma unroll
            for (int f = 0; f < 4; f++) s[n][f] = 0.f;

#pragma unroll
        for (int kk = 0; kk < 8; kk++) {
            uint32_t a[4];
            ldsm4(a[0], a[1], a[2], a[3], qa + kk * 32);
#pragma unroll
            for (int p = 0; p < 4; p++) {
                uint32_t bf0[2], bf1[2];
                ldsm4(bf0[0], bf0[1], bf1[0], bf1[1],
                      ka + (uint32_t)(p * 16 * KSTR) * 4 + kk * 32);
                mma_tf32(s[2 * p],     a, bf0);
                mma_tf32(s[2 * p + 1], a, bf1);
            }
        }

        // --- mask + scale (base-2 domain), tile row max ---
        float tmax0 = -1e30f, tmax1 = -1e30f;
#pragma unroll
        for (int n = 0; n < 8; n++) {
            const float mf0 = msf[n * 8 + 2 * lr];
            const float mf1 = msf[n * 8 + 2 * lr + 1];
            s[n][0] = fmaf(s[n][0], C, mf0);
            s[n][1] = fmaf(s[n][1], C, mf1);
            s[n][2] = fmaf(s[n][2], C, mf0);
            s[n][3] = fmaf(s[n][3], C, mf1);
            tmax0 = fmaxf(tmax0, fmaxf(s[n][0], s[n][1]));
            tmax1 = fmaxf(tmax1, fmaxf(s[n][2], s[n][3]));
        }
        tmax0 = fmaxf(tmax0, __shfl_xor_sync(0xffffffffu, tmax0, 1));
        tmax0 = fmaxf(tmax0, __shfl_xor_sync(0xffffffffu, tmax0, 2));
        tmax1 = fmaxf(tmax1, __shfl_xor_sync(0xffffffffu, tmax1, 1));
        tmax1 = fmaxf(tmax1, __shfl_xor_sync(0xffffffffu, tmax1, 2));

        const float mn0 = fmaxf(m0, tmax0);
        const float mn1 = fmaxf(m1, tmax1);
        const float c0 = fexp2(m0 - mn0);
        const float c1 = fexp2(m1 - mn1);
        m0 = mn0; m1 = mn1;
        l0 *= c0;  l1 *= c1;

        // --- p = 2^(s-m) in registers; rescale O; accumulate l ---
#pragma unroll
        for (int n = 0; n < 8; n++) {
            o[n][0] *= c0; o[n][1] *= c0; o[n][2] *= c1; o[n][3] *= c1;
            s[n][0] = fexp2(s[n][0] - m0);
            s[n][1] = fexp2(s[n][1] - m0);
            s[n][2] = fexp2(s[n][2] - m1);
            s[n][3] = fexp2(s[n][3] - m1);
            l0 += s[n][0] + s[n][1];
            l1 += s[n][2] + s[n][3];
        }

        // --- O += P . V  (A-frag from registers: {s0,s2,s1,s3}; V permuted) ---
#pragma unroll
        for (int kk = 0; kk < 8; kk++) {
            uint32_t a[4];
            a[0] = f2tf32(s[kk][0]);
            a[1] = f2tf32(s[kk][2]);
            a[2] = f2tf32(s[kk][1]);
            a[3] = f2tf32(s[kk][3]);
#pragma unroll
            for (int p = 0; p < 4; p++) {
                const int grp = (2 * kk + half) ^ jj ^ (2 * p + hv);
                uint32_t bf0[2], bf1[2];
                ldsm4(bf0[0], bf0[1], bf1[0], bf1[1],
                      vtb + (uint32_t)(p * 4096) + (uint32_t)(grp * 16));
                mma_tf32(o[2 * p],     a, bf0);
                mma_tf32(o[2 * p + 1], a, bf1);
            }
        }
    }

    // --- finalize ---
    l0 += __shfl_xor_sync(0xffffffffu, l0, 1);
    l0 += __shfl_xor_sync(0xffffffffu, l0, 2);
    l1 += __shfl_xor_sync(0xffffffffu, l1, 1);
    l1 += __shfl_xor_sync(0xffffffffu, l1, 2);
    const float inv0 = 1.0f / l0;
    const float inv1 = 1.0f / l1;

    float* Og = O + ((size_t)b * SS + q0 + wm + lq) * EE + h * DD;
#pragma unroll
    for (int n = 0; n < 8; n++) {
        *(float2*)&Og[n * 8 + 2 * lr] =
            make_float2(o[n][0] * inv0, o[n][1] * inv0);
        *(float2*)&Og[(size_t)8 * EE + n * 8 + 2 * lr] =
            make_float2(o[n][2] * inv1, o[n][3] * inv1);
    }
}

// ---------------------------------------------------------------------------
// Launch
// Inputs (metadata order): value, key_in, query, mask,
//                          Wq, bq, Wk, bk, Wv, bv, Wo, bo
// ---------------------------------------------------------------------------
extern "C" void kernel_launch(void* const* d_in, const int* in_sizes, int n_in,
                              void* d_out, int out_size)
{
    const float* value  = (const float*)d_in[0];
    const float* key_in = (const float*)d_in[1];
    const float* query  = (const float*)d_in[2];
    const int*   mask   = (const int*)  d_in[3];
    const float* Wq = (const float*)d_in[4];
    const float* bq = (const float*)d_in[5];
    const float* Wk = (const float*)d_in[6];
    const float* bk = (const float*)d_in[7];
    const float* Wv = (const float*)d_in[8];
    const float* bv = (const float*)d_in[9];
    const float* Wo = (const float*)d_in[10];
    const float* bo = (const float*)d_in[11];
    float* out = (float*)d_out;

    float *dQ, *dK, *dV, *dA;
    cudaGetSymbolAddress((void**)&dQ, g_Q);
    cudaGetSymbolAddress((void**)&dK, g_K);
    cudaGetSymbolAddress((void**)&dV, g_V);
    cudaGetSymbolAddress((void**)&dA, g_A);

    cudaFuncSetAttribute(gemm2_tf32,
                         cudaFuncAttributeMaxDynamicSharedMemorySize, G2_SMEM_BYTES);
    cudaFuncSetAttribute(flash_mma_kernel,
                         cudaFuncAttributeMaxDynamicSharedMemorySize, FA_SMEM_BYTES);

    const int M = BB * SS;   // 4096
    const int N = EE;        // 1024
    const int Kd = EE;       // 1024

    dim3 ggrid(N / BN2, M / BM2);   // (8, 16) = 128 CTAs

    gemm2_tf32<<<ggrid, 256, G2_SMEM_BYTES>>>(query,  Wq, bq, dQ, M, N, Kd);
    gemm2_tf32<<<ggrid, 256, G2_SMEM_BYTES>>>(key_in, Wk, bk, dK, M, N, Kd);
    gemm2_tf32<<<ggrid, 256, G2_SMEM_BYTES>>>(value,  Wv, bv, dV, M, N, Kd);

    dim3 fgrid(SS / 128, HH, BB);   // (8, 16, 4)
    flash_mma_kernel<<<fgrid, FA_THREADS, FA_SMEM_BYTES>>>(dQ, dK, dV, mask, dA);

    gemm2_tf32<<<ggrid, 256, G2_SMEM_BYTES>>>(dA, Wo, bo, out, M, N, Kd);
}